// round 8
// baseline (speedup 1.0000x reference)
#include <cuda_runtime.h>
#include <cuda_bf16.h>
#include <math.h>
#include <float.h>
#include <stdint.h>

#define BB    2
#define TT    2048
#define CDIM  1024
#define NH    16
#define HD    64
#define MTOT  (BB*TT)
#define N3C   (3*CDIM)
#define RANK  16
#define LSCALE 2.0f

// ---------------- portable MMA helpers ----------------
__device__ __forceinline__ uint32_t smem_u32(const void* p) {
    uint32_t a;
    asm("{ .reg .u64 t; cvta.to.shared.u64 t, %1; cvt.u32.u64 %0, t; }" : "=r"(a) : "l"(p));
    return a;
}
__device__ __forceinline__ void cpa16(uint32_t s, const void* g) {
    asm volatile("cp.async.cg.shared.global [%0], [%1], 16;" :: "r"(s), "l"(g));
}
__device__ __forceinline__ void ldx4(uint32_t* r, uint32_t a) {
    asm volatile("ldmatrix.sync.aligned.m8n8.x4.shared.b16 {%0,%1,%2,%3}, [%4];"
        : "=r"(r[0]), "=r"(r[1]), "=r"(r[2]), "=r"(r[3]) : "r"(a));
}
__device__ __forceinline__ void ldx4t(uint32_t* r, uint32_t a) {
    asm volatile("ldmatrix.sync.aligned.m8n8.x4.trans.shared.b16 {%0,%1,%2,%3}, [%4];"
        : "=r"(r[0]), "=r"(r[1]), "=r"(r[2]), "=r"(r[3]) : "r"(a));
}
__device__ __forceinline__ void mma16816(float* d, const uint32_t* a,
                                         uint32_t b0, uint32_t b1) {
    asm volatile("mma.sync.aligned.m16n8k16.row.col.f32.bf16.bf16.f32 "
        "{%0,%1,%2,%3}, {%4,%5,%6,%7}, {%8,%9}, {%0,%1,%2,%3};"
        : "+f"(d[0]), "+f"(d[1]), "+f"(d[2]), "+f"(d[3])
        : "r"(a[0]), "r"(a[1]), "r"(a[2]), "r"(a[3]), "r"(b0), "r"(b1));
}

// ---------------- scratch ----------------
__device__ __nv_bfloat16 g_x1[MTOT * CDIM];
__device__ __nv_bfloat16 g_x2[MTOT * CDIM];
__device__ __nv_bfloat16 g_a1[MTOT * CDIM];
__device__ __nv_bfloat16 g_a2[MTOT * CDIM];
__device__ __nv_bfloat16 g_wt1a[N3C * CDIM];
__device__ __nv_bfloat16 g_wt2a[N3C * CDIM];
__device__ __nv_bfloat16 g_wt1p[CDIM * CDIM];
__device__ __nv_bfloat16 g_wt2p[CDIM * CDIM];
__device__ float g_wtf[N3C * CDIM];            // fp32 W_attn^T for boundary recompute
__device__ __nv_bfloat16 g_q1[MTOT * CDIM];    // head-major planes [bh][t][64]
__device__ __nv_bfloat16 g_q2[MTOT * CDIM];
__device__ __nv_bfloat16 g_k1[MTOT * CDIM];
__device__ __nv_bfloat16 g_k2[MTOT * CDIM];
__device__ __nv_bfloat16 g_v1[MTOT * CDIM];
__device__ __nv_bfloat16 g_v2[MTOT * CDIM];
__device__ float g_mid [MTOT * RANK];
__device__ float g_mid2[MTOT * RANK];

// ---------------- split x -> bf16 hi/lo ----------------
__global__ __launch_bounds__(256) void split_kernel(
    const float* __restrict__ X, __nv_bfloat16* __restrict__ X1,
    __nv_bfloat16* __restrict__ X2, int total4)
{
    int i = blockIdx.x * 256 + threadIdx.x;
    if (i >= total4) return;
    float4 v = *(const float4*)(X + (size_t)i * 4);
    float a[4] = { v.x, v.y, v.z, v.w };
#pragma unroll
    for (int j = 0; j < 4; j++) {
        __nv_bfloat16 h1 = __float2bfloat16(a[j]);
        __nv_bfloat16 h2 = __float2bfloat16(a[j] - __bfloat162float(h1));
        X1[(size_t)i * 4 + j] = h1;
        X2[(size_t)i * 4 + j] = h2;
    }
}

// ---------------- W[K][N] -> Wt[N][K] bf16 hi/lo (+ optional fp32 copy) ----------------
__global__ __launch_bounds__(256) void wsplit_kernel(
    const float* __restrict__ W, __nv_bfloat16* __restrict__ Wt1,
    __nv_bfloat16* __restrict__ Wt2, float* __restrict__ Wtf, int N, int K)
{
    __shared__ float t[32][33];
    int tx = threadIdx.x & 31, ty = threadIdx.x >> 5;
    int n0 = blockIdx.x * 32, k0 = blockIdx.y * 32;
#pragma unroll
    for (int i = 0; i < 4; i++)
        t[ty + i * 8][tx] = W[(size_t)(k0 + ty + i * 8) * N + n0 + tx];
    __syncthreads();
#pragma unroll
    for (int i = 0; i < 4; i++) {
        int n = ty + i * 8;
        float v = t[tx][n];
        __nv_bfloat16 h1 = __float2bfloat16(v);
        __nv_bfloat16 h2 = __float2bfloat16(v - __bfloat162float(h1));
        Wt1[(size_t)(n0 + n) * K + k0 + tx] = h1;
        Wt2[(size_t)(n0 + n) * K + k0 + tx] = h2;
        if (Wtf) Wtf[(size_t)(n0 + n) * K + k0 + tx] = v;
    }
}

// ---------------- rank-16 LoRA mid (fp32 input), 4 acc chains ----------------
__global__ __launch_bounds__(256) void lora_mid_kernel(
    const float* __restrict__ A, const float* __restrict__ la,
    float* __restrict__ out)
{
    __shared__ float las[256 * RANK];
    int tid = threadIdx.x;
    int r = tid & 15;
    int row = blockIdx.x * 16 + (tid >> 4);
    const float* arow = A + (size_t)row * CDIM;
    float a0 = 0, a1 = 0, a2 = 0, a3 = 0;
    for (int kb = 0; kb < 4; kb++) {
        __syncthreads();
        for (int idx = tid; idx < 256 * RANK; idx += 256)
            las[idx] = la[kb * 256 * RANK + idx];
        __syncthreads();
        const float* ap = arow + kb * 256;
#pragma unroll 8
        for (int k = 0; k < 256; k += 4) {
            float4 x4 = *(const float4*)(ap + k);
            a0 += x4.x * las[(k + 0) * RANK + r];
            a1 += x4.y * las[(k + 1) * RANK + r];
            a2 += x4.z * las[(k + 2) * RANK + r];
            a3 += x4.w * las[(k + 3) * RANK + r];
        }
    }
    out[(size_t)row * RANK + r] = (a0 + a1) + (a2 + a3);
}

// ---------------- LoRA mid from bf16 plane pair ----------------
__global__ __launch_bounds__(256) void lora_mid2_kernel(
    const __nv_bfloat16* __restrict__ A1, const __nv_bfloat16* __restrict__ A2,
    const float* __restrict__ la, float* __restrict__ out)
{
    __shared__ float las[256 * RANK];
    int tid = threadIdx.x;
    int r = tid & 15;
    int row = blockIdx.x * 16 + (tid >> 4);
    const __nv_bfloat16* a1r = A1 + (size_t)row * CDIM;
    const __nv_bfloat16* a2r = A2 + (size_t)row * CDIM;
    float a0 = 0, a1 = 0, a2 = 0, a3 = 0;
    for (int kb = 0; kb < 4; kb++) {
        __syncthreads();
        for (int idx = tid; idx < 256 * RANK; idx += 256)
            las[idx] = la[kb * 256 * RANK + idx];
        __syncthreads();
#pragma unroll 8
        for (int k = 0; k < 256; k += 4) {
            int kg = kb * 256 + k;
            uint2 u1 = *(const uint2*)(a1r + kg);
            uint2 u2 = *(const uint2*)(a2r + kg);
            float2 p0 = __bfloat1622float2(*(const __nv_bfloat162*)&u1.x);
            float2 p1 = __bfloat1622float2(*(const __nv_bfloat162*)&u1.y);
            float2 q0 = __bfloat1622float2(*(const __nv_bfloat162*)&u2.x);
            float2 q1 = __bfloat1622float2(*(const __nv_bfloat162*)&u2.y);
            a0 += (p0.x + q0.x) * las[(k + 0) * RANK + r];
            a1 += (p0.y + q0.y) * las[(k + 1) * RANK + r];
            a2 += (p1.x + q1.x) * las[(k + 2) * RANK + r];
            a3 += (p1.y + q1.y) * las[(k + 3) * RANK + r];
        }
    }
    out[(size_t)row * RANK + r] = (a0 + a1) + (a2 + a3);
}

// ---------------- exact recompute for quant-boundary elements ----------------
__device__ __noinline__ float exact_dot(const float* __restrict__ xr,
                                        const float* __restrict__ wc,
                                        float bv, float lv)
{
    double s = 0.0;
#pragma unroll 4
    for (int k = 0; k < CDIM; k++) s = fma((double)xr[k], (double)wc[k], s);
    return (float)(s + (double)bv + (double)(LSCALE * lv));
}
__device__ __forceinline__ float fq_fix(float v, float qs, float qz, int m, int col,
        const float* xf, const float* wtf, float bv, float lv)
{
    float frac = __fdiv_rn(v, qs) + qz;
    float r = rintf(frac);
    if (0.5f - fabsf(frac - r) < 1e-3f) {
        v = exact_dot(xf + (size_t)m * CDIM, wtf + (size_t)col * CDIM, bv, lv);
        frac = __fdiv_rn(v, qs) + qz;
        r = rintf(frac);
    }
    r = fminf(fmaxf(r, 0.0f), 255.0f);
    return (r - qz) * qs;
}

// ---------------- bf16 split GEMM on mma.sync ----------------
// Block 128x64, 8 warps (4x2), warp tile 32x32, BK=32, K=1024.
#define GSTG 30720
#define GEMM_SMEM (2 * GSTG)

__global__ __launch_bounds__(256) void gemm_mma_kernel(
    const __nv_bfloat16* __restrict__ A1, const __nv_bfloat16* __restrict__ A2,
    const __nv_bfloat16* __restrict__ B1, const __nv_bfloat16* __restrict__ B2,
    const float* __restrict__ bias,
    const float* __restrict__ mid, const float* __restrict__ lb,
    float* __restrict__ C, int N, int is_qkv,
    const float* __restrict__ qsp, const float* __restrict__ qzp,
    const float* __restrict__ xf, const float* __restrict__ wtf,
    __nv_bfloat16* __restrict__ q1p, __nv_bfloat16* __restrict__ q2p,
    __nv_bfloat16* __restrict__ k1p, __nv_bfloat16* __restrict__ k2p,
    __nv_bfloat16* __restrict__ v1p, __nv_bfloat16* __restrict__ v2p)
{
    extern __shared__ __align__(128) char sm8[];
    int tid = threadIdx.x, wid = tid >> 5, lane = tid & 31;
    int warp_m = wid & 3, warp_n = wid >> 2;
    int m0 = blockIdx.y * 128, n0 = blockIdx.x * 64;
    uint32_t sb = smem_u32(sm8);

    float acc[2][4][4];
#pragma unroll
    for (int mf = 0; mf < 2; mf++)
#pragma unroll
        for (int j = 0; j < 4; j++)
#pragma unroll
            for (int e = 0; e < 4; e++) acc[mf][j][e] = 0.0f;

    int arow0 = (tid * 2) >> 2,      acq0 = (tid * 2) & 3;
    int arow1 = (tid * 2 + 1) >> 2,  acq1 = (tid * 2 + 1) & 3;
    int brow  = tid >> 2,            bcq  = tid & 3;
    const __nv_bfloat16* pA1 = A1 + (size_t)m0 * CDIM;
    const __nv_bfloat16* pA2 = A2 + (size_t)m0 * CDIM;
    const __nv_bfloat16* pB1 = B1 + (size_t)n0 * CDIM;
    const __nv_bfloat16* pB2 = B2 + (size_t)n0 * CDIM;

#define LOAD_STAGE(buf, kc) do { \
    uint32_t st_ = sb + (buf) * GSTG; \
    cpa16(st_ + arow0 * 80 + acq0 * 16,          pA1 + (size_t)arow0 * CDIM + (kc) + acq0 * 8); \
    cpa16(st_ + arow1 * 80 + acq1 * 16,          pA1 + (size_t)arow1 * CDIM + (kc) + acq1 * 8); \
    cpa16(st_ + 10240 + arow0 * 80 + acq0 * 16,  pA2 + (size_t)arow0 * CDIM + (kc) + acq0 * 8); \
    cpa16(st_ + 10240 + arow1 * 80 + acq1 * 16,  pA2 + (size_t)arow1 * CDIM + (kc) + acq1 * 8); \
    cpa16(st_ + 20480 + brow * 80 + bcq * 16,    pB1 + (size_t)brow * CDIM + (kc) + bcq * 8); \
    cpa16(st_ + 25600 + brow * 80 + bcq * 16,    pB2 + (size_t)brow * CDIM + (kc) + bcq * 8); \
    asm volatile("cp.async.commit_group;" ::: "memory"); \
} while (0)

    LOAD_STAGE(0, 0);

    for (int s = 0; s < 32; s++) {
        if (s + 1 < 32) {
            LOAD_STAGE((s + 1) & 1, (s + 1) * 32);
            asm volatile("cp.async.wait_group 1;" ::: "memory");
        } else {
            asm volatile("cp.async.wait_group 0;" ::: "memory");
        }
        __syncthreads();

        uint32_t st = sb + (s & 1) * GSTG;
        uint32_t aoff = st + (uint32_t)(warp_m * 32 + (lane & 15)) * 80 + (uint32_t)(lane >> 4) * 16;
        uint32_t boff = st + 20480 +
            (uint32_t)(warp_n * 32 + (lane & 7) + ((lane >> 4) & 1) * 8) * 80 +
            (uint32_t)((lane >> 3) & 1) * 16;
#pragma unroll
        for (int kk = 0; kk < 2; kk++) {
            uint32_t ko = kk * 32;
            uint32_t a1f[2][4], a2f[2][4], b1f[2][4], b2f[2][4];
#pragma unroll
            for (int mf = 0; mf < 2; mf++) {
                ldx4(a1f[mf], aoff + mf * 1280 + ko);
                ldx4(a2f[mf], aoff + 10240 + mf * 1280 + ko);
            }
#pragma unroll
            for (int nf = 0; nf < 2; nf++) {
                ldx4(b1f[nf], boff + nf * 1280 + ko);
                ldx4(b2f[nf], boff + 5120 + nf * 1280 + ko);
            }
#pragma unroll
            for (int mf = 0; mf < 2; mf++)
#pragma unroll
                for (int j = 0; j < 4; j++) {
                    int nf = j >> 1, sub = (j & 1) * 2;
                    mma16816(acc[mf][j], a1f[mf], b1f[nf][sub], b1f[nf][sub + 1]);
                    mma16816(acc[mf][j], a1f[mf], b2f[nf][sub], b2f[nf][sub + 1]);
                    mma16816(acc[mf][j], a2f[mf], b1f[nf][sub], b1f[nf][sub + 1]);
                }
        }
        __syncthreads();
    }

    // ---- epilogue ----
    float* sMid = (float*)sm8;            // [128][16]
    float* sLb  = (float*)(sm8 + 8192);   // [16][64]
    for (int idx = tid; idx < 128 * RANK; idx += 256) {
        int row = idx >> 4, r = idx & 15;
        sMid[idx] = mid[(size_t)(m0 + row) * RANK + r];
    }
    for (int idx = tid; idx < RANK * 64; idx += 256) {
        int r = idx >> 6, c = idx & 63;
        sLb[idx] = lb[(size_t)r * N + n0 + c];
    }
    __syncthreads();

    float qs = is_qkv ? *qsp : 1.0f, qz = is_qkv ? *qzp : 0.0f;
    int group = lane >> 2, tig = lane & 3;
#pragma unroll
    for (int mf = 0; mf < 2; mf++) {
#pragma unroll
        for (int half = 0; half < 2; half++) {
            int rloc = warp_m * 32 + mf * 16 + group + half * 8;
#pragma unroll
            for (int j = 0; j < 4; j++) {
                int cloc = warp_n * 32 + j * 8 + tig * 2;
                float d0 = acc[mf][j][half * 2];
                float d1 = acc[mf][j][half * 2 + 1];
                float lv0 = 0.0f, lv1 = 0.0f;
#pragma unroll
                for (int r = 0; r < RANK; r++) {
                    float mv = sMid[rloc * RANK + r];
                    lv0 += mv * sLb[r * 64 + cloc];
                    lv1 += mv * sLb[r * 64 + cloc + 1];
                }
                float bv0 = bias[n0 + cloc], bv1 = bias[n0 + cloc + 1];
                float v0 = d0 + bv0 + LSCALE * lv0;
                float v1 = d1 + bv1 + LSCALE * lv1;
                int m = m0 + rloc;
                int col = n0 + cloc;
                if (!is_qkv) {
                    *(float2*)&C[(size_t)m * N + col] = make_float2(v0, v1);
                } else {
                    int bq = m >> 11, t = m & 2047;
                    if (col < CDIM) {
                        int h = col >> 6, d = col & 63;
                        size_t off = (((size_t)(bq * NH + h)) * TT + t) * HD + d;
                        float s0 = v0 * 0.125f, s1 = v1 * 0.125f;
                        __nv_bfloat162 h1 = __floats2bfloat162_rn(s0, s1);
                        float2 hf = __bfloat1622float2(h1);
                        __nv_bfloat162 h2 = __floats2bfloat162_rn(s0 - hf.x, s1 - hf.y);
                        *(__nv_bfloat162*)(q1p + off) = h1;
                        *(__nv_bfloat162*)(q2p + off) = h2;
                    } else {
                        int cc = col - CDIM;
                        __nv_bfloat16 *p1, *p2;
                        if (cc < CDIM) { p1 = k1p; p2 = k2p; }
                        else           { p1 = v1p; p2 = v2p; cc -= CDIM; }
                        v0 = fq_fix(v0, qs, qz, m, col,     xf, wtf, bv0, lv0);
                        v1 = fq_fix(v1, qs, qz, m, col + 1, xf, wtf, bv1, lv1);
                        int h = cc >> 6, d = cc & 63;
                        size_t off = (((size_t)(bq * NH + h)) * TT + t) * HD + d;
                        __nv_bfloat162 h1 = __floats2bfloat162_rn(v0, v1);
                        float2 hf = __bfloat1622float2(h1);
                        __nv_bfloat162 h2 = __floats2bfloat162_rn(v0 - hf.x, v1 - hf.y);
                        *(__nv_bfloat162*)(p1 + off) = h1;
                        *(__nv_bfloat162*)(p2 + off) = h2;
                    }
                }
            }
        }
    }
}

// ---------------- HMMA flash attention ----------------
// 128 threads (4 warps, 16 q-rows each), 64x64 tiles, split-bf16 S and PV.
// smem: Q1 @0, Q2 @9216, stages @18432 + st*36864: K1,K2,V1,V2 (9216 each).
#define ATTN_SMEM 92160

__global__ __launch_bounds__(128) void attn_kernel(
    const __nv_bfloat16* __restrict__ q1p, const __nv_bfloat16* __restrict__ q2p,
    const __nv_bfloat16* __restrict__ k1p, const __nv_bfloat16* __restrict__ k2p,
    const __nv_bfloat16* __restrict__ v1p, const __nv_bfloat16* __restrict__ v2p,
    __nv_bfloat16* __restrict__ a1p, __nv_bfloat16* __restrict__ a2p)
{
    extern __shared__ __align__(128) char smx[];
    uint32_t sb = smem_u32(smx);
    int tid = threadIdx.x, lane = tid & 31, w = tid >> 5;
    int bh = blockIdx.x;
    int qb = (int)gridDim.y - 1 - (int)blockIdx.y;
    size_t hbase = (size_t)bh * TT * HD;
    int group = lane >> 2, tig = lane & 3;

    // Q load (rows qb*64..)
#pragma unroll
    for (int c = 0; c < 4; c++) {
        int ch = c * 128 + tid; int row = ch >> 3, cq = ch & 7;
        size_t g = hbase + (size_t)(qb * 64 + row) * HD + cq * 8;
        uint32_t so = row * 144 + cq * 16;
        cpa16(sb + so,        q1p + g);
        cpa16(sb + 9216 + so, q2p + g);
    }
#define LOADKV(buf, jb) do { \
    uint32_t s0_ = sb + 18432 + (buf) * 36864; \
    _Pragma("unroll") \
    for (int c = 0; c < 4; c++) { \
        int ch = c * 128 + tid; int row = ch >> 3, cq = ch & 7; \
        size_t g = hbase + (size_t)((jb) * 64 + row) * HD + cq * 8; \
        uint32_t so = row * 144 + cq * 16; \
        cpa16(s0_ + so,         k1p + g); \
        cpa16(s0_ + 9216 + so,  k2p + g); \
        cpa16(s0_ + 18432 + so, v1p + g); \
        cpa16(s0_ + 27648 + so, v2p + g); \
    } \
} while (0)
    LOADKV(0, 0);
    asm volatile("cp.async.commit_group;" ::: "memory");

    uint32_t q1f[4][4], q2f[4][4];
    float mrow[2] = { -1e30f, -1e30f }, lrow[2] = { 0.0f, 0.0f };
    float oacc[8][4];
#pragma unroll
    for (int nb = 0; nb < 8; nb++)
#pragma unroll
        for (int e = 0; e < 4; e++) oacc[nb][e] = 0.0f;

    for (int j = 0; j <= qb; j++) {
        if (j < qb) {
            LOADKV((j + 1) & 1, j + 1);
            asm volatile("cp.async.commit_group;" ::: "memory");
            asm volatile("cp.async.wait_group 1;" ::: "memory");
        } else {
            asm volatile("cp.async.wait_group 0;" ::: "memory");
        }
        __syncthreads();

        if (j == 0) {   // hoist Q fragments once
            uint32_t qa = sb + (uint32_t)(w * 16 + (lane & 15)) * 144 + (uint32_t)(lane >> 4) * 16;
#pragma unroll
            for (int kk = 0; kk < 4; kk++) {
                ldx4(q1f[kk], qa + kk * 32);
                ldx4(q2f[kk], qa + 9216 + kk * 32);
            }
        }

        uint32_t stg = sb + 18432 + (uint32_t)(j & 1) * 36864;

        // S = Q K^T (3 split terms)
        float sacc[8][4];
#pragma unroll
        for (int nb = 0; nb < 8; nb++)
#pragma unroll
            for (int e = 0; e < 4; e++) sacc[nb][e] = 0.0f;
#pragma unroll
        for (int kk = 0; kk < 4; kk++) {
#pragma unroll
            for (int nbp = 0; nbp < 4; nbp++) {
                uint32_t ka = stg + (uint32_t)(nbp * 16 + (lane & 7) + ((lane >> 4) & 1) * 8) * 144
                            + (uint32_t)((lane >> 3) & 1) * 16 + kk * 32;
                uint32_t kf1[4], kf2[4];
                ldx4(kf1, ka);
                ldx4(kf2, ka + 9216);
#pragma unroll
                for (int h = 0; h < 2; h++) {
                    int nb = nbp * 2 + h, sub = h * 2;
                    mma16816(sacc[nb], q1f[kk], kf1[sub], kf1[sub + 1]);
                    mma16816(sacc[nb], q1f[kk], kf2[sub], kf2[sub + 1]);
                    mma16816(sacc[nb], q2f[kk], kf1[sub], kf1[sub + 1]);
                }
            }
        }

        // causal mask on diagonal block
        if (j == qb) {
#pragma unroll
            for (int nb = 0; nb < 8; nb++)
#pragma unroll
                for (int e = 0; e < 2; e++) {
                    int rowl = w * 16 + group + e * 8;
                    int c0 = nb * 8 + tig * 2;
                    if (c0 > rowl)     sacc[nb][e * 2]     = -1e30f;
                    if (c0 + 1 > rowl) sacc[nb][e * 2 + 1] = -1e30f;
                }
        }

        // streaming softmax on fragments
        float mx[2] = { -1e30f, -1e30f };
#pragma unroll
        for (int nb = 0; nb < 8; nb++) {
            mx[0] = fmaxf(mx[0], fmaxf(sacc[nb][0], sacc[nb][1]));
            mx[1] = fmaxf(mx[1], fmaxf(sacc[nb][2], sacc[nb][3]));
        }
#pragma unroll
        for (int o = 1; o <= 2; o <<= 1) {
            mx[0] = fmaxf(mx[0], __shfl_xor_sync(0xffffffffu, mx[0], o));
            mx[1] = fmaxf(mx[1], __shfl_xor_sync(0xffffffffu, mx[1], o));
        }
        float al[2];
#pragma unroll
        for (int e = 0; e < 2; e++) {
            float mn = fmaxf(mrow[e], mx[e]);
            al[e] = __expf(mrow[e] - mn);
            mrow[e] = mn;
        }
        float rs[2] = { 0.0f, 0.0f };
#pragma unroll
        for (int nb = 0; nb < 8; nb++) {
#pragma unroll
            for (int e = 0; e < 2; e++) {
                float p0 = __expf(sacc[nb][e * 2]     - mrow[e]);
                float p1 = __expf(sacc[nb][e * 2 + 1] - mrow[e]);
                sacc[nb][e * 2] = p0; sacc[nb][e * 2 + 1] = p1;
                rs[e] += p0 + p1;
            }
        }
#pragma unroll
        for (int o = 1; o <= 2; o <<= 1) {
            rs[0] += __shfl_xor_sync(0xffffffffu, rs[0], o);
            rs[1] += __shfl_xor_sync(0xffffffffu, rs[1], o);
        }
#pragma unroll
        for (int e = 0; e < 2; e++) lrow[e] = lrow[e] * al[e] + rs[e];
#pragma unroll
        for (int nb = 0; nb < 8; nb++) {
            oacc[nb][0] *= al[0]; oacc[nb][1] *= al[0];
            oacc[nb][2] *= al[1]; oacc[nb][3] *= al[1];
        }

        // O += P V (FA2 register repack, 3 split terms)
#pragma unroll
        for (int kk = 0; kk < 4; kk++) {
            int t0 = 2 * kk, t1 = 2 * kk + 1;
            uint32_t pa1[4], pa2[4];
            {
                __nv_bfloat162 h;
                float2 hf;
                h = __floats2bfloat162_rn(sacc[t0][0], sacc[t0][1]);
                hf = __bfloat1622float2(h); pa1[0] = *(uint32_t*)&h;
                h = __floats2bfloat162_rn(sacc[t0][0] - hf.x, sacc[t0][1] - hf.y);
                pa2[0] = *(uint32_t*)&h;
                h = __floats2bfloat162_rn(sacc[t0][2], sacc[t0][3]);
                hf = __bfloat1622float2(h); pa1[1] = *(uint32_t*)&h;
                h = __floats2bfloat162_rn(sacc[t0][2] - hf.x, sacc[t0][3] - hf.y);
                pa2[1] = *(uint32_t*)&h;
                h = __floats2bfloat162_rn(sacc[t1][0], sacc[t1][1]);
                hf = __bfloat1622float2(h); pa1[2] = *(uint32_t*)&h;
                h = __floats2bfloat162_rn(sacc[t1][0] - hf.x, sacc[t1][1] - hf.y);
                pa2[2] = *(uint32_t*)&h;
                h = __floats2bfloat162_rn(sacc[t1][2], sacc[t1][3]);
                hf = __bfloat1622float2(h); pa1[3] = *(uint32_t*)&h;
                h = __floats2bfloat162_rn(sacc[t1][2] - hf.x, sacc[t1][3] - hf.y);
                pa2[3] = *(uint32_t*)&h;
            }
#pragma unroll
            for (int nbp = 0; nbp < 4; nbp++) {
                uint32_t va = stg + 18432
                    + (uint32_t)(kk * 16 + (lane & 7) + ((lane >> 3) & 1) * 8) * 144
                    + nbp * 32 + (uint32_t)(lane >> 4) * 16;
                uint32_t vf1[4], vf2[4];
                ldx4t(vf1, va);
                ldx4t(vf2, va + 9216);
                mma16816(oacc[2 * nbp],     pa1, vf1[0], vf1[1]);
                mma16816(oacc[2 * nbp],     pa1, vf2[0], vf2[1]);
                mma16816(oacc[2 * nbp],     pa2, vf1[0], vf1[1]);
                mma16816(oacc[2 * nbp + 1], pa1, vf1[2], vf1[3]);
                mma16816(oacc[2 * nbp + 1], pa1, vf2[2], vf2[3]);
                mma16816(oacc[2 * nbp + 1], pa2, vf1[2], vf1[3]);
            }
        }
        __syncthreads();
    }

    // finalize: write bf16 split planes (token-major [m][1024]) for proj GEMM
    int b = bh >> 4, h = bh & 15;
#pragma unroll
    for (int e = 0; e < 2; e++) {
        float inv = __fdiv_rn(1.0f, lrow[e]);
        int t = qb * 64 + w * 16 + group + e * 8;
        size_t mrow_off = ((size_t)(b * TT + t)) * CDIM + h * HD;
#pragma unroll
        for (int nb = 0; nb < 8; nb++) {
            float o0 = oacc[nb][e * 2] * inv;
            float o1 = oacc[nb][e * 2 + 1] * inv;
            int d = nb * 8 + tig * 2;
            __nv_bfloat162 h1 = __floats2bfloat162_rn(o0, o1);
            float2 hf = __bfloat1622float2(h1);
            __nv_bfloat162 h2 = __floats2bfloat162_rn(o0 - hf.x, o1 - hf.y);
            *(__nv_bfloat162*)(a1p + mrow_off + d) = h1;
            *(__nv_bfloat162*)(a2p + mrow_off + d) = h2;
        }
    }
}

// ---------------- launch ----------------
extern "C" void kernel_launch(void* const* d_in, const int* in_sizes, int n_in,
                              void* d_out, int out_size)
{
    const float* x       = (const float*)d_in[0];
    const float* w_attn  = (const float*)d_in[1];
    const float* b_attn  = (const float*)d_in[2];
    const float* la_attn = (const float*)d_in[3];
    const float* lb_attn = (const float*)d_in[4];
    const float* w_proj  = (const float*)d_in[5];
    const float* b_proj  = (const float*)d_in[6];
    const float* la_proj = (const float*)d_in[7];
    const float* lb_proj = (const float*)d_in[8];
    const float* ksc     = (const float*)d_in[9];
    const float* kzp     = (const float*)d_in[10];
    float* out = (float*)d_out;

    void* p;
    cudaGetSymbolAddress(&p, g_x1);   __nv_bfloat16* x1 = (__nv_bfloat16*)p;
    cudaGetSymbolAddress(&p, g_x2);   __nv_bfloat16* x2 = (__nv_bfloat16*)p;
    cudaGetSymbolAddress(&p, g_a1);   __nv_bfloat16* a1 = (__nv_bfloat16*)p;
    cudaGetSymbolAddress(&p, g_a2);   __nv_bfloat16* a2 = (__nv_bfloat16*)p;
    cudaGetSymbolAddress(&p, g_wt1a); __nv_bfloat16* wt1a = (__nv_bfloat16*)p;
    cudaGetSymbolAddress(&p, g_wt2a); __nv_bfloat16* wt2a = (__nv_bfloat16*)p;
    cudaGetSymbolAddress(&p, g_wt1p); __nv_bfloat16* wt1p = (__nv_bfloat16*)p;
    cudaGetSymbolAddress(&p, g_wt2p); __nv_bfloat16* wt2p = (__nv_bfloat16*)p;
    cudaGetSymbolAddress(&p, g_wtf);  float* wtf = (float*)p;
    cudaGetSymbolAddress(&p, g_q1);   __nv_bfloat16* q1 = (__nv_bfloat16*)p;
    cudaGetSymbolAddress(&p, g_q2);   __nv_bfloat16* q2 = (__nv_bfloat16*)p;
    cudaGetSymbolAddress(&p, g_k1);   __nv_bfloat16* k1 = (__nv_bfloat16*)p;
    cudaGetSymbolAddress(&p, g_k2);   __nv_bfloat16* k2 = (__nv_bfloat16*)p;
    cudaGetSymbolAddress(&p, g_v1);   __nv_bfloat16* v1 = (__nv_bfloat16*)p;
    cudaGetSymbolAddress(&p, g_v2);   __nv_bfloat16* v2 = (__nv_bfloat16*)p;
    cudaGetSymbolAddress(&p, g_mid);  float* mid  = (float*)p;
    cudaGetSymbolAddress(&p, g_mid2); float* mid2 = (float*)p;

    cudaFuncSetAttribute(gemm_mma_kernel,
                         cudaFuncAttributeMaxDynamicSharedMemorySize, GEMM_SMEM);
    cudaFuncSetAttribute(attn_kernel,
                         cudaFuncAttributeMaxDynamicSharedMemorySize, ATTN_SMEM);

    split_kernel<<<(MTOT * CDIM / 4 + 255) / 256, 256>>>(x, x1, x2, MTOT * CDIM / 4);
    wsplit_kernel<<<dim3(N3C / 32, CDIM / 32), 256>>>(w_attn, wt1a, wt2a, wtf, N3C, CDIM);
    wsplit_kernel<<<dim3(CDIM / 32, CDIM / 32), 256>>>(w_proj, wt1p, wt2p, (float*)0, CDIM, CDIM);
    lora_mid_kernel<<<MTOT / 16, 256>>>(x, la_attn, mid);
    gemm_mma_kernel<<<dim3(N3C / 64, MTOT / 128), 256, GEMM_SMEM>>>(
        x1, x2, wt1a, wt2a, b_attn, mid, lb_attn,
        (float*)0, N3C, 1, ksc, kzp, x, wtf, q1, q2, k1, k2, v1, v2);
    attn_kernel<<<dim3(BB * NH, TT / 64), 128, ATTN_SMEM>>>(
        q1, q2, k1, k2, v1, v2, a1, a2);
    lora_mid2_kernel<<<MTOT / 16, 256>>>(a1, a2, la_proj, mid2);
    gemm_mma_kernel<<<dim3(CDIM / 64, MTOT / 128), 256, GEMM_SMEM>>>(
        a1, a2, wt1p, wt2p, b_proj, mid2, lb_proj,
        out, CDIM, 0, ksc, kzp, x, wtf,
        (__nv_bfloat16*)0, (__nv_bfloat16*)0, (__nv_bfloat16*)0,
        (__nv_bfloat16*)0, (__nv_bfloat16*)0, (__nv_bfloat16*)0);
}

// round 9
// speedup vs baseline: 4.9295x; 4.9295x over previous
#include <cuda_runtime.h>
#include <cuda_bf16.h>
#include <math.h>
#include <float.h>
#include <stdint.h>

#define BB    2
#define TT    2048
#define CDIM  1024
#define NH    16
#define HD    64
#define MTOT  (BB*TT)
#define N3C   (3*CDIM)
#define RANK  16
#define LSCALE 2.0f

// ---------------- portable MMA helpers ----------------
__device__ __forceinline__ uint32_t smem_u32(const void* p) {
    uint32_t a;
    asm("{ .reg .u64 t; cvta.to.shared.u64 t, %1; cvt.u32.u64 %0, t; }" : "=r"(a) : "l"(p));
    return a;
}
__device__ __forceinline__ void cpa16(uint32_t s, const void* g) {
    asm volatile("cp.async.cg.shared.global [%0], [%1], 16;" :: "r"(s), "l"(g));
}
__device__ __forceinline__ void ldx4(uint32_t* r, uint32_t a) {
    asm volatile("ldmatrix.sync.aligned.m8n8.x4.shared.b16 {%0,%1,%2,%3}, [%4];"
        : "=r"(r[0]), "=r"(r[1]), "=r"(r[2]), "=r"(r[3]) : "r"(a));
}
__device__ __forceinline__ void ldx4t(uint32_t* r, uint32_t a) {
    asm volatile("ldmatrix.sync.aligned.m8n8.x4.trans.shared.b16 {%0,%1,%2,%3}, [%4];"
        : "=r"(r[0]), "=r"(r[1]), "=r"(r[2]), "=r"(r[3]) : "r"(a));
}
__device__ __forceinline__ void mma16816(float* d, const uint32_t* a,
                                         uint32_t b0, uint32_t b1) {
    asm volatile("mma.sync.aligned.m16n8k16.row.col.f32.bf16.bf16.f32 "
        "{%0,%1,%2,%3}, {%4,%5,%6,%7}, {%8,%9}, {%0,%1,%2,%3};"
        : "+f"(d[0]), "+f"(d[1]), "+f"(d[2]), "+f"(d[3])
        : "r"(a[0]), "r"(a[1]), "r"(a[2]), "r"(a[3]), "r"(b0), "r"(b1));
}

// ---------------- scratch ----------------
__device__ __nv_bfloat16 g_x1[MTOT * CDIM];
__device__ __nv_bfloat16 g_x2[MTOT * CDIM];
__device__ __nv_bfloat16 g_a1[MTOT * CDIM];
__device__ __nv_bfloat16 g_a2[MTOT * CDIM];
__device__ __nv_bfloat16 g_wt1a[N3C * CDIM];
__device__ __nv_bfloat16 g_wt2a[N3C * CDIM];
__device__ __nv_bfloat16 g_wt1p[CDIM * CDIM];
__device__ __nv_bfloat16 g_wt2p[CDIM * CDIM];
__device__ float g_wtf[N3C * CDIM];            // fp32 W_attn^T for boundary recompute
__device__ __nv_bfloat16 g_q1[MTOT * CDIM];    // head-major planes [bh][t][64]
__device__ __nv_bfloat16 g_q2[MTOT * CDIM];
__device__ __nv_bfloat16 g_k1[MTOT * CDIM];
__device__ __nv_bfloat16 g_k2[MTOT * CDIM];
__device__ __nv_bfloat16 g_v1[MTOT * CDIM];
__device__ __nv_bfloat16 g_v2[MTOT * CDIM];
__device__ float g_mid [MTOT * RANK];
__device__ float g_mid2[MTOT * RANK];

// ---------------- split x -> bf16 hi/lo ----------------
__global__ __launch_bounds__(256) void split_kernel(
    const float* __restrict__ X, __nv_bfloat16* __restrict__ X1,
    __nv_bfloat16* __restrict__ X2, int total4)
{
    int i = blockIdx.x * 256 + threadIdx.x;
    if (i >= total4) return;
    float4 v = *(const float4*)(X + (size_t)i * 4);
    float a[4] = { v.x, v.y, v.z, v.w };
#pragma unroll
    for (int j = 0; j < 4; j++) {
        __nv_bfloat16 h1 = __float2bfloat16(a[j]);
        __nv_bfloat16 h2 = __float2bfloat16(a[j] - __bfloat162float(h1));
        X1[(size_t)i * 4 + j] = h1;
        X2[(size_t)i * 4 + j] = h2;
    }
}

// ---------------- W[K][N] -> Wt[N][K] bf16 hi/lo (+ optional fp32 copy) ----------------
__global__ __launch_bounds__(256) void wsplit_kernel(
    const float* __restrict__ W, __nv_bfloat16* __restrict__ Wt1,
    __nv_bfloat16* __restrict__ Wt2, float* __restrict__ Wtf, int N, int K)
{
    __shared__ float t[32][33];
    int tx = threadIdx.x & 31, ty = threadIdx.x >> 5;
    int n0 = blockIdx.x * 32, k0 = blockIdx.y * 32;
#pragma unroll
    for (int i = 0; i < 4; i++)
        t[ty + i * 8][tx] = W[(size_t)(k0 + ty + i * 8) * N + n0 + tx];
    __syncthreads();
#pragma unroll
    for (int i = 0; i < 4; i++) {
        int n = ty + i * 8;
        float v = t[tx][n];
        __nv_bfloat16 h1 = __float2bfloat16(v);
        __nv_bfloat16 h2 = __float2bfloat16(v - __bfloat162float(h1));
        Wt1[(size_t)(n0 + n) * K + k0 + tx] = h1;
        Wt2[(size_t)(n0 + n) * K + k0 + tx] = h2;
        if (Wtf) Wtf[(size_t)(n0 + n) * K + k0 + tx] = v;
    }
}

// ---------------- rank-16 LoRA mid (fp32 input), 4 acc chains ----------------
__global__ __launch_bounds__(256) void lora_mid_kernel(
    const float* __restrict__ A, const float* __restrict__ la,
    float* __restrict__ out)
{
    __shared__ float las[256 * RANK];
    int tid = threadIdx.x;
    int r = tid & 15;
    int row = blockIdx.x * 16 + (tid >> 4);
    const float* arow = A + (size_t)row * CDIM;
    float a0 = 0, a1 = 0, a2 = 0, a3 = 0;
    for (int kb = 0; kb < 4; kb++) {
        __syncthreads();
        for (int idx = tid; idx < 256 * RANK; idx += 256)
            las[idx] = la[kb * 256 * RANK + idx];
        __syncthreads();
        const float* ap = arow + kb * 256;
#pragma unroll 8
        for (int k = 0; k < 256; k += 4) {
            float4 x4 = *(const float4*)(ap + k);
            a0 += x4.x * las[(k + 0) * RANK + r];
            a1 += x4.y * las[(k + 1) * RANK + r];
            a2 += x4.z * las[(k + 2) * RANK + r];
            a3 += x4.w * las[(k + 3) * RANK + r];
        }
    }
    out[(size_t)row * RANK + r] = (a0 + a1) + (a2 + a3);
}

// ---------------- LoRA mid from bf16 plane pair ----------------
__global__ __launch_bounds__(256) void lora_mid2_kernel(
    const __nv_bfloat16* __restrict__ A1, const __nv_bfloat16* __restrict__ A2,
    const float* __restrict__ la, float* __restrict__ out)
{
    __shared__ float las[256 * RANK];
    int tid = threadIdx.x;
    int r = tid & 15;
    int row = blockIdx.x * 16 + (tid >> 4);
    const __nv_bfloat16* a1r = A1 + (size_t)row * CDIM;
    const __nv_bfloat16* a2r = A2 + (size_t)row * CDIM;
    float a0 = 0, a1 = 0, a2 = 0, a3 = 0;
    for (int kb = 0; kb < 4; kb++) {
        __syncthreads();
        for (int idx = tid; idx < 256 * RANK; idx += 256)
            las[idx] = la[kb * 256 * RANK + idx];
        __syncthreads();
#pragma unroll 8
        for (int k = 0; k < 256; k += 4) {
            int kg = kb * 256 + k;
            uint2 u1 = *(const uint2*)(a1r + kg);
            uint2 u2 = *(const uint2*)(a2r + kg);
            float2 p0 = __bfloat1622float2(*(const __nv_bfloat162*)&u1.x);
            float2 p1 = __bfloat1622float2(*(const __nv_bfloat162*)&u1.y);
            float2 q0 = __bfloat1622float2(*(const __nv_bfloat162*)&u2.x);
            float2 q1 = __bfloat1622float2(*(const __nv_bfloat162*)&u2.y);
            a0 += (p0.x + q0.x) * las[(k + 0) * RANK + r];
            a1 += (p0.y + q0.y) * las[(k + 1) * RANK + r];
            a2 += (p1.x + q1.x) * las[(k + 2) * RANK + r];
            a3 += (p1.y + q1.y) * las[(k + 3) * RANK + r];
        }
    }
    out[(size_t)row * RANK + r] = (a0 + a1) + (a2 + a3);
}

// ---------------- fp32 recompute for quant-boundary elements ----------------
// 8 independent chains + float4 ldg: ~1-2K cycles per call (vs 48K for fp64 serial).
__device__ __noinline__ float exact_dot(const float* __restrict__ xr,
                                        const float* __restrict__ wc,
                                        float bv, float lv)
{
    float s0 = 0, s1 = 0, s2 = 0, s3 = 0, s4 = 0, s5 = 0, s6 = 0, s7 = 0;
#pragma unroll 4
    for (int k = 0; k < CDIM; k += 8) {
        float4 xa = __ldg((const float4*)(xr + k));
        float4 xb = __ldg((const float4*)(xr + k + 4));
        float4 wa = __ldg((const float4*)(wc + k));
        float4 wb = __ldg((const float4*)(wc + k + 4));
        s0 += xa.x * wa.x; s1 += xa.y * wa.y;
        s2 += xa.z * wa.z; s3 += xa.w * wa.w;
        s4 += xb.x * wb.x; s5 += xb.y * wb.y;
        s6 += xb.z * wb.z; s7 += xb.w * wb.w;
    }
    return ((s0 + s1) + (s2 + s3)) + ((s4 + s5) + (s6 + s7)) + bv + LSCALE * lv;
}
__device__ __forceinline__ float fq_fix(float v, float qs, float qz, int m, int col,
        const float* xf, const float* wtf, float bv, float lv)
{
    float frac = __fdiv_rn(v, qs) + qz;
    float r = rintf(frac);
    if (0.5f - fabsf(frac - r) < 1e-3f) {
        v = exact_dot(xf + (size_t)m * CDIM, wtf + (size_t)col * CDIM, bv, lv);
        frac = __fdiv_rn(v, qs) + qz;
        r = rintf(frac);
    }
    r = fminf(fmaxf(r, 0.0f), 255.0f);
    return (r - qz) * qs;
}

// ---------------- bf16 split GEMM on mma.sync ----------------
// Block 128x64, 8 warps (4x2), warp tile 32x32, BK=32, K=1024.
#define GSTG 30720
#define GEMM_SMEM (2 * GSTG)

__global__ __launch_bounds__(256) void gemm_mma_kernel(
    const __nv_bfloat16* __restrict__ A1, const __nv_bfloat16* __restrict__ A2,
    const __nv_bfloat16* __restrict__ B1, const __nv_bfloat16* __restrict__ B2,
    const float* __restrict__ bias,
    const float* __restrict__ mid, const float* __restrict__ lb,
    float* __restrict__ C, int N, int is_qkv,
    const float* __restrict__ qsp, const float* __restrict__ qzp,
    const float* __restrict__ xf, const float* __restrict__ wtf,
    __nv_bfloat16* __restrict__ q1p, __nv_bfloat16* __restrict__ q2p,
    __nv_bfloat16* __restrict__ k1p, __nv_bfloat16* __restrict__ k2p,
    __nv_bfloat16* __restrict__ v1p, __nv_bfloat16* __restrict__ v2p)
{
    extern __shared__ __align__(128) char sm8[];
    int tid = threadIdx.x, wid = tid >> 5, lane = tid & 31;
    int warp_m = wid & 3, warp_n = wid >> 2;
    int m0 = blockIdx.y * 128, n0 = blockIdx.x * 64;
    uint32_t sb = smem_u32(sm8);

    float acc[2][4][4];
#pragma unroll
    for (int mf = 0; mf < 2; mf++)
#pragma unroll
        for (int j = 0; j < 4; j++)
#pragma unroll
            for (int e = 0; e < 4; e++) acc[mf][j][e] = 0.0f;

    int arow0 = (tid * 2) >> 2,      acq0 = (tid * 2) & 3;
    int arow1 = (tid * 2 + 1) >> 2,  acq1 = (tid * 2 + 1) & 3;
    int brow  = tid >> 2,            bcq  = tid & 3;
    const __nv_bfloat16* pA1 = A1 + (size_t)m0 * CDIM;
    const __nv_bfloat16* pA2 = A2 + (size_t)m0 * CDIM;
    const __nv_bfloat16* pB1 = B1 + (size_t)n0 * CDIM;
    const __nv_bfloat16* pB2 = B2 + (size_t)n0 * CDIM;

#define LOAD_STAGE(buf, kc) do { \
    uint32_t st_ = sb + (buf) * GSTG; \
    cpa16(st_ + arow0 * 80 + acq0 * 16,          pA1 + (size_t)arow0 * CDIM + (kc) + acq0 * 8); \
    cpa16(st_ + arow1 * 80 + acq1 * 16,          pA1 + (size_t)arow1 * CDIM + (kc) + acq1 * 8); \
    cpa16(st_ + 10240 + arow0 * 80 + acq0 * 16,  pA2 + (size_t)arow0 * CDIM + (kc) + acq0 * 8); \
    cpa16(st_ + 10240 + arow1 * 80 + acq1 * 16,  pA2 + (size_t)arow1 * CDIM + (kc) + acq1 * 8); \
    cpa16(st_ + 20480 + brow * 80 + bcq * 16,    pB1 + (size_t)brow * CDIM + (kc) + bcq * 8); \
    cpa16(st_ + 25600 + brow * 80 + bcq * 16,    pB2 + (size_t)brow * CDIM + (kc) + bcq * 8); \
    asm volatile("cp.async.commit_group;" ::: "memory"); \
} while (0)

    LOAD_STAGE(0, 0);

    for (int s = 0; s < 32; s++) {
        if (s + 1 < 32) {
            LOAD_STAGE((s + 1) & 1, (s + 1) * 32);
            asm volatile("cp.async.wait_group 1;" ::: "memory");
        } else {
            asm volatile("cp.async.wait_group 0;" ::: "memory");
        }
        __syncthreads();

        uint32_t st = sb + (s & 1) * GSTG;
        uint32_t aoff = st + (uint32_t)(warp_m * 32 + (lane & 15)) * 80 + (uint32_t)(lane >> 4) * 16;
        uint32_t boff = st + 20480 +
            (uint32_t)(warp_n * 32 + (lane & 7) + ((lane >> 4) & 1) * 8) * 80 +
            (uint32_t)((lane >> 3) & 1) * 16;
#pragma unroll
        for (int kk = 0; kk < 2; kk++) {
            uint32_t ko = kk * 32;
            uint32_t a1f[2][4], a2f[2][4], b1f[2][4], b2f[2][4];
#pragma unroll
            for (int mf = 0; mf < 2; mf++) {
                ldx4(a1f[mf], aoff + mf * 1280 + ko);
                ldx4(a2f[mf], aoff + 10240 + mf * 1280 + ko);
            }
#pragma unroll
            for (int nf = 0; nf < 2; nf++) {
                ldx4(b1f[nf], boff + nf * 1280 + ko);
                ldx4(b2f[nf], boff + 5120 + nf * 1280 + ko);
            }
#pragma unroll
            for (int mf = 0; mf < 2; mf++)
#pragma unroll
                for (int j = 0; j < 4; j++) {
                    int nf = j >> 1, sub = (j & 1) * 2;
                    mma16816(acc[mf][j], a1f[mf], b1f[nf][sub], b1f[nf][sub + 1]);
                    mma16816(acc[mf][j], a1f[mf], b2f[nf][sub], b2f[nf][sub + 1]);
                    mma16816(acc[mf][j], a2f[mf], b1f[nf][sub], b1f[nf][sub + 1]);
                }
        }
        __syncthreads();
    }

    // ---- epilogue ----
    float* sMid = (float*)sm8;            // [128][16]
    float* sLb  = (float*)(sm8 + 8192);   // [16][64]
    for (int idx = tid; idx < 128 * RANK; idx += 256) {
        int row = idx >> 4, r = idx & 15;
        sMid[idx] = mid[(size_t)(m0 + row) * RANK + r];
    }
    for (int idx = tid; idx < RANK * 64; idx += 256) {
        int r = idx >> 6, c = idx & 63;
        sLb[idx] = lb[(size_t)r * N + n0 + c];
    }
    __syncthreads();

    float qs = is_qkv ? *qsp : 1.0f, qz = is_qkv ? *qzp : 0.0f;
    int group = lane >> 2, tig = lane & 3;
#pragma unroll
    for (int mf = 0; mf < 2; mf++) {
#pragma unroll
        for (int half = 0; half < 2; half++) {
            int rloc = warp_m * 32 + mf * 16 + group + half * 8;
#pragma unroll
            for (int j = 0; j < 4; j++) {
                int cloc = warp_n * 32 + j * 8 + tig * 2;
                float d0 = acc[mf][j][half * 2];
                float d1 = acc[mf][j][half * 2 + 1];
                float lv0 = 0.0f, lv1 = 0.0f;
#pragma unroll
                for (int r = 0; r < RANK; r++) {
                    float mv = sMid[rloc * RANK + r];
                    lv0 += mv * sLb[r * 64 + cloc];
                    lv1 += mv * sLb[r * 64 + cloc + 1];
                }
                float bv0 = bias[n0 + cloc], bv1 = bias[n0 + cloc + 1];
                float v0 = d0 + bv0 + LSCALE * lv0;
                float v1 = d1 + bv1 + LSCALE * lv1;
                int m = m0 + rloc;
                int col = n0 + cloc;
                if (!is_qkv) {
                    *(float2*)&C[(size_t)m * N + col] = make_float2(v0, v1);
                } else {
                    int bq = m >> 11, t = m & 2047;
                    if (col < CDIM) {
                        int h = col >> 6, d = col & 63;
                        size_t off = (((size_t)(bq * NH + h)) * TT + t) * HD + d;
                        float s0 = v0 * 0.125f, s1 = v1 * 0.125f;
                        __nv_bfloat162 h1 = __floats2bfloat162_rn(s0, s1);
                        float2 hf = __bfloat1622float2(h1);
                        __nv_bfloat162 h2 = __floats2bfloat162_rn(s0 - hf.x, s1 - hf.y);
                        *(__nv_bfloat162*)(q1p + off) = h1;
                        *(__nv_bfloat162*)(q2p + off) = h2;
                    } else {
                        int cc = col - CDIM;
                        __nv_bfloat16 *p1, *p2;
                        if (cc < CDIM) { p1 = k1p; p2 = k2p; }
                        else           { p1 = v1p; p2 = v2p; cc -= CDIM; }
                        v0 = fq_fix(v0, qs, qz, m, col,     xf, wtf, bv0, lv0);
                        v1 = fq_fix(v1, qs, qz, m, col + 1, xf, wtf, bv1, lv1);
                        int h = cc >> 6, d = cc & 63;
                        size_t off = (((size_t)(bq * NH + h)) * TT + t) * HD + d;
                        __nv_bfloat162 h1 = __floats2bfloat162_rn(v0, v1);
                        float2 hf = __bfloat1622float2(h1);
                        __nv_bfloat162 h2 = __floats2bfloat162_rn(v0 - hf.x, v1 - hf.y);
                        *(__nv_bfloat162*)(p1 + off) = h1;
                        *(__nv_bfloat162*)(p2 + off) = h2;
                    }
                }
            }
        }
    }
}

// ---------------- HMMA flash attention ----------------
// 128 threads (4 warps, 16 q-rows each), 64x64 tiles, split-bf16 S and PV.
// smem: Q1 @0, Q2 @9216, stages @18432 + st*36864: K1,K2,V1,V2 (9216 each).
#define ATTN_SMEM 92160

__global__ __launch_bounds__(128) void attn_kernel(
    const __nv_bfloat16* __restrict__ q1p, const __nv_bfloat16* __restrict__ q2p,
    const __nv_bfloat16* __restrict__ k1p, const __nv_bfloat16* __restrict__ k2p,
    const __nv_bfloat16* __restrict__ v1p, const __nv_bfloat16* __restrict__ v2p,
    __nv_bfloat16* __restrict__ a1p, __nv_bfloat16* __restrict__ a2p)
{
    extern __shared__ __align__(128) char smx[];
    uint32_t sb = smem_u32(smx);
    int tid = threadIdx.x, lane = tid & 31, w = tid >> 5;
    int bh = blockIdx.x;
    int qb = (int)gridDim.y - 1 - (int)blockIdx.y;
    size_t hbase = (size_t)bh * TT * HD;
    int group = lane >> 2, tig = lane & 3;

    // Q load (rows qb*64..)
#pragma unroll
    for (int c = 0; c < 4; c++) {
        int ch = c * 128 + tid; int row = ch >> 3, cq = ch & 7;
        size_t g = hbase + (size_t)(qb * 64 + row) * HD + cq * 8;
        uint32_t so = row * 144 + cq * 16;
        cpa16(sb + so,        q1p + g);
        cpa16(sb + 9216 + so, q2p + g);
    }
#define LOADKV(buf, jb) do { \
    uint32_t s0_ = sb + 18432 + (buf) * 36864; \
    _Pragma("unroll") \
    for (int c = 0; c < 4; c++) { \
        int ch = c * 128 + tid; int row = ch >> 3, cq = ch & 7; \
        size_t g = hbase + (size_t)((jb) * 64 + row) * HD + cq * 8; \
        uint32_t so = row * 144 + cq * 16; \
        cpa16(s0_ + so,         k1p + g); \
        cpa16(s0_ + 9216 + so,  k2p + g); \
        cpa16(s0_ + 18432 + so, v1p + g); \
        cpa16(s0_ + 27648 + so, v2p + g); \
    } \
} while (0)
    LOADKV(0, 0);
    asm volatile("cp.async.commit_group;" ::: "memory");

    uint32_t q1f[4][4], q2f[4][4];
    float mrow[2] = { -1e30f, -1e30f }, lrow[2] = { 0.0f, 0.0f };
    float oacc[8][4];
#pragma unroll
    for (int nb = 0; nb < 8; nb++)
#pragma unroll
        for (int e = 0; e < 4; e++) oacc[nb][e] = 0.0f;

    for (int j = 0; j <= qb; j++) {
        if (j < qb) {
            LOADKV((j + 1) & 1, j + 1);
            asm volatile("cp.async.commit_group;" ::: "memory");
            asm volatile("cp.async.wait_group 1;" ::: "memory");
        } else {
            asm volatile("cp.async.wait_group 0;" ::: "memory");
        }
        __syncthreads();

        if (j == 0) {   // hoist Q fragments once
            uint32_t qa = sb + (uint32_t)(w * 16 + (lane & 15)) * 144 + (uint32_t)(lane >> 4) * 16;
#pragma unroll
            for (int kk = 0; kk < 4; kk++) {
                ldx4(q1f[kk], qa + kk * 32);
                ldx4(q2f[kk], qa + 9216 + kk * 32);
            }
        }

        uint32_t stg = sb + 18432 + (uint32_t)(j & 1) * 36864;

        // S = Q K^T (3 split terms)
        float sacc[8][4];
#pragma unroll
        for (int nb = 0; nb < 8; nb++)
#pragma unroll
            for (int e = 0; e < 4; e++) sacc[nb][e] = 0.0f;
#pragma unroll
        for (int kk = 0; kk < 4; kk++) {
#pragma unroll
            for (int nbp = 0; nbp < 4; nbp++) {
                uint32_t ka = stg + (uint32_t)(nbp * 16 + (lane & 7) + ((lane >> 4) & 1) * 8) * 144
                            + (uint32_t)((lane >> 3) & 1) * 16 + kk * 32;
                uint32_t kf1[4], kf2[4];
                ldx4(kf1, ka);
                ldx4(kf2, ka + 9216);
#pragma unroll
                for (int h = 0; h < 2; h++) {
                    int nb = nbp * 2 + h, sub = h * 2;
                    mma16816(sacc[nb], q1f[kk], kf1[sub], kf1[sub + 1]);
                    mma16816(sacc[nb], q1f[kk], kf2[sub], kf2[sub + 1]);
                    mma16816(sacc[nb], q2f[kk], kf1[sub], kf1[sub + 1]);
                }
            }
        }

        // causal mask on diagonal block
        if (j == qb) {
#pragma unroll
            for (int nb = 0; nb < 8; nb++)
#pragma unroll
                for (int e = 0; e < 2; e++) {
                    int rowl = w * 16 + group + e * 8;
                    int c0 = nb * 8 + tig * 2;
                    if (c0 > rowl)     sacc[nb][e * 2]     = -1e30f;
                    if (c0 + 1 > rowl) sacc[nb][e * 2 + 1] = -1e30f;
                }
        }

        // streaming softmax on fragments
        float mx[2] = { -1e30f, -1e30f };
#pragma unroll
        for (int nb = 0; nb < 8; nb++) {
            mx[0] = fmaxf(mx[0], fmaxf(sacc[nb][0], sacc[nb][1]));
            mx[1] = fmaxf(mx[1], fmaxf(sacc[nb][2], sacc[nb][3]));
        }
#pragma unroll
        for (int o = 1; o <= 2; o <<= 1) {
            mx[0] = fmaxf(mx[0], __shfl_xor_sync(0xffffffffu, mx[0], o));
            mx[1] = fmaxf(mx[1], __shfl_xor_sync(0xffffffffu, mx[1], o));
        }
        float al[2];
#pragma unroll
        for (int e = 0; e < 2; e++) {
            float mn = fmaxf(mrow[e], mx[e]);
            al[e] = __expf(mrow[e] - mn);
            mrow[e] = mn;
        }
        float rs[2] = { 0.0f, 0.0f };
#pragma unroll
        for (int nb = 0; nb < 8; nb++) {
#pragma unroll
            for (int e = 0; e < 2; e++) {
                float p0 = __expf(sacc[nb][e * 2]     - mrow[e]);
                float p1 = __expf(sacc[nb][e * 2 + 1] - mrow[e]);
                sacc[nb][e * 2] = p0; sacc[nb][e * 2 + 1] = p1;
                rs[e] += p0 + p1;
            }
        }
#pragma unroll
        for (int o = 1; o <= 2; o <<= 1) {
            rs[0] += __shfl_xor_sync(0xffffffffu, rs[0], o);
            rs[1] += __shfl_xor_sync(0xffffffffu, rs[1], o);
        }
#pragma unroll
        for (int e = 0; e < 2; e++) lrow[e] = lrow[e] * al[e] + rs[e];
#pragma unroll
        for (int nb = 0; nb < 8; nb++) {
            oacc[nb][0] *= al[0]; oacc[nb][1] *= al[0];
            oacc[nb][2] *= al[1]; oacc[nb][3] *= al[1];
        }

        // O += P V (FA2 register repack, 3 split terms)
#pragma unroll
        for (int kk = 0; kk < 4; kk++) {
            int t0 = 2 * kk, t1 = 2 * kk + 1;
            uint32_t pa1[4], pa2[4];
            {
                __nv_bfloat162 h;
                float2 hf;
                h = __floats2bfloat162_rn(sacc[t0][0], sacc[t0][1]);
                hf = __bfloat1622float2(h); pa1[0] = *(uint32_t*)&h;
                h = __floats2bfloat162_rn(sacc[t0][0] - hf.x, sacc[t0][1] - hf.y);
                pa2[0] = *(uint32_t*)&h;
                h = __floats2bfloat162_rn(sacc[t0][2], sacc[t0][3]);
                hf = __bfloat1622float2(h); pa1[1] = *(uint32_t*)&h;
                h = __floats2bfloat162_rn(sacc[t0][2] - hf.x, sacc[t0][3] - hf.y);
                pa2[1] = *(uint32_t*)&h;
                h = __floats2bfloat162_rn(sacc[t1][0], sacc[t1][1]);
                hf = __bfloat1622float2(h); pa1[2] = *(uint32_t*)&h;
                h = __floats2bfloat162_rn(sacc[t1][0] - hf.x, sacc[t1][1] - hf.y);
                pa2[2] = *(uint32_t*)&h;
                h = __floats2bfloat162_rn(sacc[t1][2], sacc[t1][3]);
                hf = __bfloat1622float2(h); pa1[3] = *(uint32_t*)&h;
                h = __floats2bfloat162_rn(sacc[t1][2] - hf.x, sacc[t1][3] - hf.y);
                pa2[3] = *(uint32_t*)&h;
            }
#pragma unroll
            for (int nbp = 0; nbp < 4; nbp++) {
                uint32_t va = stg + 18432
                    + (uint32_t)(kk * 16 + (lane & 7) + ((lane >> 3) & 1) * 8) * 144
                    + nbp * 32 + (uint32_t)(lane >> 4) * 16;
                uint32_t vf1[4], vf2[4];
                ldx4t(vf1, va);
                ldx4t(vf2, va + 9216);
                mma16816(oacc[2 * nbp],     pa1, vf1[0], vf1[1]);
                mma16816(oacc[2 * nbp],     pa1, vf2[0], vf2[1]);
                mma16816(oacc[2 * nbp],     pa2, vf1[0], vf1[1]);
                mma16816(oacc[2 * nbp + 1], pa1, vf1[2], vf1[3]);
                mma16816(oacc[2 * nbp + 1], pa1, vf2[2], vf2[3]);
                mma16816(oacc[2 * nbp + 1], pa2, vf1[2], vf1[3]);
            }
        }
        __syncthreads();
    }

    // finalize: write bf16 split planes (token-major [m][1024]) for proj GEMM
    int b = bh >> 4, h = bh & 15;
#pragma unroll
    for (int e = 0; e < 2; e++) {
        float inv = __fdiv_rn(1.0f, lrow[e]);
        int t = qb * 64 + w * 16 + group + e * 8;
        size_t mrow_off = ((size_t)(b * TT + t)) * CDIM + h * HD;
#pragma unroll
        for (int nb = 0; nb < 8; nb++) {
            float o0 = oacc[nb][e * 2] * inv;
            float o1 = oacc[nb][e * 2 + 1] * inv;
            int d = nb * 8 + tig * 2;
            __nv_bfloat162 h1 = __floats2bfloat162_rn(o0, o1);
            float2 hf = __bfloat1622float2(h1);
            __nv_bfloat162 h2 = __floats2bfloat162_rn(o0 - hf.x, o1 - hf.y);
            *(__nv_bfloat162*)(a1p + mrow_off + d) = h1;
            *(__nv_bfloat162*)(a2p + mrow_off + d) = h2;
        }
    }
}

// ---------------- launch ----------------
extern "C" void kernel_launch(void* const* d_in, const int* in_sizes, int n_in,
                              void* d_out, int out_size)
{
    const float* x       = (const float*)d_in[0];
    const float* w_attn  = (const float*)d_in[1];
    const float* b_attn  = (const float*)d_in[2];
    const float* la_attn = (const float*)d_in[3];
    const float* lb_attn = (const float*)d_in[4];
    const float* w_proj  = (const float*)d_in[5];
    const float* b_proj  = (const float*)d_in[6];
    const float* la_proj = (const float*)d_in[7];
    const float* lb_proj = (const float*)d_in[8];
    const float* ksc     = (const float*)d_in[9];
    const float* kzp     = (const float*)d_in[10];
    float* out = (float*)d_out;

    void* p;
    cudaGetSymbolAddress(&p, g_x1);   __nv_bfloat16* x1 = (__nv_bfloat16*)p;
    cudaGetSymbolAddress(&p, g_x2);   __nv_bfloat16* x2 = (__nv_bfloat16*)p;
    cudaGetSymbolAddress(&p, g_a1);   __nv_bfloat16* a1 = (__nv_bfloat16*)p;
    cudaGetSymbolAddress(&p, g_a2);   __nv_bfloat16* a2 = (__nv_bfloat16*)p;
    cudaGetSymbolAddress(&p, g_wt1a); __nv_bfloat16* wt1a = (__nv_bfloat16*)p;
    cudaGetSymbolAddress(&p, g_wt2a); __nv_bfloat16* wt2a = (__nv_bfloat16*)p;
    cudaGetSymbolAddress(&p, g_wt1p); __nv_bfloat16* wt1p = (__nv_bfloat16*)p;
    cudaGetSymbolAddress(&p, g_wt2p); __nv_bfloat16* wt2p = (__nv_bfloat16*)p;
    cudaGetSymbolAddress(&p, g_wtf);  float* wtf = (float*)p;
    cudaGetSymbolAddress(&p, g_q1);   __nv_bfloat16* q1 = (__nv_bfloat16*)p;
    cudaGetSymbolAddress(&p, g_q2);   __nv_bfloat16* q2 = (__nv_bfloat16*)p;
    cudaGetSymbolAddress(&p, g_k1);   __nv_bfloat16* k1 = (__nv_bfloat16*)p;
    cudaGetSymbolAddress(&p, g_k2);   __nv_bfloat16* k2 = (__nv_bfloat16*)p;
    cudaGetSymbolAddress(&p, g_v1);   __nv_bfloat16* v1 = (__nv_bfloat16*)p;
    cudaGetSymbolAddress(&p, g_v2);   __nv_bfloat16* v2 = (__nv_bfloat16*)p;
    cudaGetSymbolAddress(&p, g_mid);  float* mid  = (float*)p;
    cudaGetSymbolAddress(&p, g_mid2); float* mid2 = (float*)p;

    cudaFuncSetAttribute(gemm_mma_kernel,
                         cudaFuncAttributeMaxDynamicSharedMemorySize, GEMM_SMEM);
    cudaFuncSetAttribute(attn_kernel,
                         cudaFuncAttributeMaxDynamicSharedMemorySize, ATTN_SMEM);

    split_kernel<<<(MTOT * CDIM / 4 + 255) / 256, 256>>>(x, x1, x2, MTOT * CDIM / 4);
    wsplit_kernel<<<dim3(N3C / 32, CDIM / 32), 256>>>(w_attn, wt1a, wt2a, wtf, N3C, CDIM);
    wsplit_kernel<<<dim3(CDIM / 32, CDIM / 32), 256>>>(w_proj, wt1p, wt2p, (float*)0, CDIM, CDIM);
    lora_mid_kernel<<<MTOT / 16, 256>>>(x, la_attn, mid);
    gemm_mma_kernel<<<dim3(N3C / 64, MTOT / 128), 256, GEMM_SMEM>>>(
        x1, x2, wt1a, wt2a, b_attn, mid, lb_attn,
        (float*)0, N3C, 1, ksc, kzp, x, wtf, q1, q2, k1, k2, v1, v2);
    attn_kernel<<<dim3(BB * NH, TT / 64), 128, ATTN_SMEM>>>(
        q1, q2, k1, k2, v1, v2, a1, a2);
    lora_mid2_kernel<<<MTOT / 16, 256>>>(a1, a2, la_proj, mid2);
    gemm_mma_kernel<<<dim3(CDIM / 64, MTOT / 128), 256, GEMM_SMEM>>>(
        a1, a2, wt1p, wt2p, b_proj, mid2, lb_proj,
        out, CDIM, 0, ksc, kzp, x, wtf,
        (__nv_bfloat16*)0, (__nv_bfloat16*)0, (__nv_bfloat16*)0,
        (__nv_bfloat16*)0, (__nv_bfloat16*)0, (__nv_bfloat16*)0);
}

// round 11
// speedup vs baseline: 5.2566x; 1.0664x over previous
#include <cuda_runtime.h>
#include <cuda_bf16.h>
#include <math.h>
#include <float.h>
#include <stdint.h>

#define BB    2
#define TT    2048
#define CDIM  1024
#define NH    16
#define HD    64
#define MTOT  (BB*TT)
#define N3C   (3*CDIM)
#define RANK  16
#define LSCALE 2.0f

// ---------------- portable MMA helpers ----------------
__device__ __forceinline__ uint32_t smem_u32(const void* p) {
    uint32_t a;
    asm("{ .reg .u64 t; cvta.to.shared.u64 t, %1; cvt.u32.u64 %0, t; }" : "=r"(a) : "l"(p));
    return a;
}
__device__ __forceinline__ void cpa16(uint32_t s, const void* g) {
    asm volatile("cp.async.cg.shared.global [%0], [%1], 16;" :: "r"(s), "l"(g));
}
__device__ __forceinline__ void ldx4(uint32_t* r, uint32_t a) {
    asm volatile("ldmatrix.sync.aligned.m8n8.x4.shared.b16 {%0,%1,%2,%3}, [%4];"
        : "=r"(r[0]), "=r"(r[1]), "=r"(r[2]), "=r"(r[3]) : "r"(a));
}
__device__ __forceinline__ void ldx4t(uint32_t* r, uint32_t a) {
    asm volatile("ldmatrix.sync.aligned.m8n8.x4.trans.shared.b16 {%0,%1,%2,%3}, [%4];"
        : "=r"(r[0]), "=r"(r[1]), "=r"(r[2]), "=r"(r[3]) : "r"(a));
}
__device__ __forceinline__ void mma16816(float* d, const uint32_t* a,
                                         uint32_t b0, uint32_t b1) {
    asm volatile("mma.sync.aligned.m16n8k16.row.col.f32.bf16.bf16.f32 "
        "{%0,%1,%2,%3}, {%4,%5,%6,%7}, {%8,%9}, {%0,%1,%2,%3};"
        : "+f"(d[0]), "+f"(d[1]), "+f"(d[2]), "+f"(d[3])
        : "r"(a[0]), "r"(a[1]), "r"(a[2]), "r"(a[3]), "r"(b0), "r"(b1));
}

// ---------------- scratch ----------------
__device__ __nv_bfloat16 g_x1[MTOT * CDIM];
__device__ __nv_bfloat16 g_x2[MTOT * CDIM];
__device__ __nv_bfloat16 g_a1[MTOT * CDIM];
__device__ __nv_bfloat16 g_a2[MTOT * CDIM];
__device__ __nv_bfloat16 g_wt1a[N3C * CDIM];
__device__ __nv_bfloat16 g_wt2a[N3C * CDIM];
__device__ __nv_bfloat16 g_wt1p[CDIM * CDIM];
__device__ __nv_bfloat16 g_wt2p[CDIM * CDIM];
__device__ float g_wtf[N3C * CDIM];            // fp32 W_attn^T for boundary recompute
__device__ __nv_bfloat16 g_q1[MTOT * CDIM];    // head-major planes [bh][t][64]
__device__ __nv_bfloat16 g_q2[MTOT * CDIM];
__device__ __nv_bfloat16 g_kq[MTOT * CDIM];    // K as exact integer levels (r - zp)
__device__ __nv_bfloat16 g_vq[MTOT * CDIM];    // V as exact integer levels (r - zp)
__device__ float g_mid [MTOT * RANK];
__device__ float g_mid2[MTOT * RANK];

// ---------------- split x -> bf16 hi/lo ----------------
__global__ __launch_bounds__(256) void split_kernel(
    const float* __restrict__ X, __nv_bfloat16* __restrict__ X1,
    __nv_bfloat16* __restrict__ X2, int total4)
{
    int i = blockIdx.x * 256 + threadIdx.x;
    if (i >= total4) return;
    float4 v = *(const float4*)(X + (size_t)i * 4);
    float a[4] = { v.x, v.y, v.z, v.w };
#pragma unroll
    for (int j = 0; j < 4; j++) {
        __nv_bfloat16 h1 = __float2bfloat16(a[j]);
        __nv_bfloat16 h2 = __float2bfloat16(a[j] - __bfloat162float(h1));
        X1[(size_t)i * 4 + j] = h1;
        X2[(size_t)i * 4 + j] = h2;
    }
}

// ---------------- W[K][N] -> Wt[N][K] bf16 hi/lo (+ optional fp32 copy) ----------------
__global__ __launch_bounds__(256) void wsplit_kernel(
    const float* __restrict__ W, __nv_bfloat16* __restrict__ Wt1,
    __nv_bfloat16* __restrict__ Wt2, float* __restrict__ Wtf, int N, int K)
{
    __shared__ float t[32][33];
    int tx = threadIdx.x & 31, ty = threadIdx.x >> 5;
    int n0 = blockIdx.x * 32, k0 = blockIdx.y * 32;
#pragma unroll
    for (int i = 0; i < 4; i++)
        t[ty + i * 8][tx] = W[(size_t)(k0 + ty + i * 8) * N + n0 + tx];
    __syncthreads();
#pragma unroll
    for (int i = 0; i < 4; i++) {
        int n = ty + i * 8;
        float v = t[tx][n];
        __nv_bfloat16 h1 = __float2bfloat16(v);
        __nv_bfloat16 h2 = __float2bfloat16(v - __bfloat162float(h1));
        Wt1[(size_t)(n0 + n) * K + k0 + tx] = h1;
        Wt2[(size_t)(n0 + n) * K + k0 + tx] = h2;
        if (Wtf) Wtf[(size_t)(n0 + n) * K + k0 + tx] = v;
    }
}

// ---------------- rank-16 LoRA mid: la fully staged (64KB) ----------------
#define LORA_SMEM (CDIM * RANK * 4)

__global__ __launch_bounds__(256) void lora_mid_kernel(
    const float* __restrict__ A, const float* __restrict__ la,
    float* __restrict__ out)
{
    extern __shared__ float las[];
    int tid = threadIdx.x;
    int r = tid & 15;
    int row = blockIdx.x * 16 + (tid >> 4);
    for (int idx = tid; idx < CDIM * RANK; idx += 256)
        las[idx] = la[idx];
    __syncthreads();
    const float* ap = A + (size_t)row * CDIM;
    float a0 = 0, a1 = 0, a2 = 0, a3 = 0;
#pragma unroll 8
    for (int k = 0; k < CDIM; k += 4) {
        float4 x4 = *(const float4*)(ap + k);
        a0 += x4.x * las[(k + 0) * RANK + r];
        a1 += x4.y * las[(k + 1) * RANK + r];
        a2 += x4.z * las[(k + 2) * RANK + r];
        a3 += x4.w * las[(k + 3) * RANK + r];
    }
    out[(size_t)row * RANK + r] = (a0 + a1) + (a2 + a3);
}

__global__ __launch_bounds__(256) void lora_mid2_kernel(
    const __nv_bfloat16* __restrict__ A1, const __nv_bfloat16* __restrict__ A2,
    const float* __restrict__ la, float* __restrict__ out)
{
    extern __shared__ float las[];
    int tid = threadIdx.x;
    int r = tid & 15;
    int row = blockIdx.x * 16 + (tid >> 4);
    for (int idx = tid; idx < CDIM * RANK; idx += 256)
        las[idx] = la[idx];
    __syncthreads();
    const __nv_bfloat16* a1r = A1 + (size_t)row * CDIM;
    const __nv_bfloat16* a2r = A2 + (size_t)row * CDIM;
    float a0 = 0, a1 = 0, a2 = 0, a3 = 0;
#pragma unroll 8
    for (int k = 0; k < CDIM; k += 4) {
        uint2 u1 = *(const uint2*)(a1r + k);
        uint2 u2 = *(const uint2*)(a2r + k);
        float2 p0 = __bfloat1622float2(*(const __nv_bfloat162*)&u1.x);
        float2 p1 = __bfloat1622float2(*(const __nv_bfloat162*)&u1.y);
        float2 q0 = __bfloat1622float2(*(const __nv_bfloat162*)&u2.x);
        float2 q1 = __bfloat1622float2(*(const __nv_bfloat162*)&u2.y);
        a0 += (p0.x + q0.x) * las[(k + 0) * RANK + r];
        a1 += (p0.y + q0.y) * las[(k + 1) * RANK + r];
        a2 += (p1.x + q1.x) * las[(k + 2) * RANK + r];
        a3 += (p1.y + q1.y) * las[(k + 3) * RANK + r];
    }
    out[(size_t)row * RANK + r] = (a0 + a1) + (a2 + a3);
}

// ---------------- fp32 recompute for quant-boundary elements ----------------
__device__ __noinline__ float exact_dot(const float* __restrict__ xr,
                                        const float* __restrict__ wc,
                                        float bv, float lv)
{
    float s0 = 0, s1 = 0, s2 = 0, s3 = 0, s4 = 0, s5 = 0, s6 = 0, s7 = 0;
#pragma unroll 4
    for (int k = 0; k < CDIM; k += 8) {
        float4 xa = __ldg((const float4*)(xr + k));
        float4 xb = __ldg((const float4*)(xr + k + 4));
        float4 wa = __ldg((const float4*)(wc + k));
        float4 wb = __ldg((const float4*)(wc + k + 4));
        s0 += xa.x * wa.x; s1 += xa.y * wa.y;
        s2 += xa.z * wa.z; s3 += xa.w * wa.w;
        s4 += xb.x * wb.x; s5 += xb.y * wb.y;
        s6 += xb.z * wb.z; s7 += xb.w * wb.w;
    }
    return ((s0 + s1) + (s2 + s3)) + ((s4 + s5) + (s6 + s7)) + bv + LSCALE * lv;
}
// returns clamped quant LEVEL r (plane stores r - qz, exact integer in bf16)
__device__ __forceinline__ float fq_level(float v, float qs, float qz, int m, int col,
        const float* xf, const float* wtf, float bv, float lv)
{
    float frac = __fdiv_rn(v, qs) + qz;
    float r = rintf(frac);
    if (0.5f - fabsf(frac - r) < 1e-3f) {
        v = exact_dot(xf + (size_t)m * CDIM, wtf + (size_t)col * CDIM, bv, lv);
        frac = __fdiv_rn(v, qs) + qz;
        r = rintf(frac);
    }
    return fminf(fmaxf(r, 0.0f), 255.0f);
}

// ---------------- bf16 split GEMM on mma.sync ----------------
// Block 128x64, 8 warps (4x2), warp tile 32x32, BK=32, K=1024.
#define GSTG 30720
#define GEMM_SMEM (2 * GSTG)

__global__ __launch_bounds__(256) void gemm_mma_kernel(
    const __nv_bfloat16* __restrict__ A1, const __nv_bfloat16* __restrict__ A2,
    const __nv_bfloat16* __restrict__ B1, const __nv_bfloat16* __restrict__ B2,
    const float* __restrict__ bias,
    const float* __restrict__ mid, const float* __restrict__ lb,
    float* __restrict__ C, int N, int is_qkv,
    const float* __restrict__ qsp, const float* __restrict__ qzp,
    const float* __restrict__ xf, const float* __restrict__ wtf,
    __nv_bfloat16* __restrict__ q1p, __nv_bfloat16* __restrict__ q2p,
    __nv_bfloat16* __restrict__ kqp, __nv_bfloat16* __restrict__ vqp)
{
    extern __shared__ __align__(128) char sm8[];
    int tid = threadIdx.x, wid = tid >> 5, lane = tid & 31;
    int warp_m = wid & 3, warp_n = wid >> 2;
    int m0 = blockIdx.y * 128, n0 = blockIdx.x * 64;
    uint32_t sb = smem_u32(sm8);

    float acc[2][4][4];
#pragma unroll
    for (int mf = 0; mf < 2; mf++)
#pragma unroll
        for (int j = 0; j < 4; j++)
#pragma unroll
            for (int e = 0; e < 4; e++) acc[mf][j][e] = 0.0f;

    int arow0 = (tid * 2) >> 2,      acq0 = (tid * 2) & 3;
    int arow1 = (tid * 2 + 1) >> 2,  acq1 = (tid * 2 + 1) & 3;
    int brow  = tid >> 2,            bcq  = tid & 3;
    const __nv_bfloat16* pA1 = A1 + (size_t)m0 * CDIM;
    const __nv_bfloat16* pA2 = A2 + (size_t)m0 * CDIM;
    const __nv_bfloat16* pB1 = B1 + (size_t)n0 * CDIM;
    const __nv_bfloat16* pB2 = B2 + (size_t)n0 * CDIM;

#define LOAD_STAGE(buf, kc) do { \
    uint32_t st_ = sb + (buf) * GSTG; \
    cpa16(st_ + arow0 * 80 + acq0 * 16,          pA1 + (size_t)arow0 * CDIM + (kc) + acq0 * 8); \
    cpa16(st_ + arow1 * 80 + acq1 * 16,          pA1 + (size_t)arow1 * CDIM + (kc) + acq1 * 8); \
    cpa16(st_ + 10240 + arow0 * 80 + acq0 * 16,  pA2 + (size_t)arow0 * CDIM + (kc) + acq0 * 8); \
    cpa16(st_ + 10240 + arow1 * 80 + acq1 * 16,  pA2 + (size_t)arow1 * CDIM + (kc) + acq1 * 8); \
    cpa16(st_ + 20480 + brow * 80 + bcq * 16,    pB1 + (size_t)brow * CDIM + (kc) + bcq * 8); \
    cpa16(st_ + 25600 + brow * 80 + bcq * 16,    pB2 + (size_t)brow * CDIM + (kc) + bcq * 8); \
    asm volatile("cp.async.commit_group;" ::: "memory"); \
} while (0)

    LOAD_STAGE(0, 0);

    for (int s = 0; s < 32; s++) {
        if (s + 1 < 32) {
            LOAD_STAGE((s + 1) & 1, (s + 1) * 32);
            asm volatile("cp.async.wait_group 1;" ::: "memory");
        } else {
            asm volatile("cp.async.wait_group 0;" ::: "memory");
        }
        __syncthreads();

        uint32_t st = sb + (s & 1) * GSTG;
        uint32_t aoff = st + (uint32_t)(warp_m * 32 + (lane & 15)) * 80 + (uint32_t)(lane >> 4) * 16;
        uint32_t boff = st + 20480 +
            (uint32_t)(warp_n * 32 + (lane & 7) + ((lane >> 4) & 1) * 8) * 80 +
            (uint32_t)((lane >> 3) & 1) * 16;
#pragma unroll
        for (int kk = 0; kk < 2; kk++) {
            uint32_t ko = kk * 32;
            uint32_t a1f[2][4], a2f[2][4], b1f[2][4], b2f[2][4];
#pragma unroll
            for (int mf = 0; mf < 2; mf++) {
                ldx4(a1f[mf], aoff + mf * 1280 + ko);
                ldx4(a2f[mf], aoff + 10240 + mf * 1280 + ko);
            }
#pragma unroll
            for (int nf = 0; nf < 2; nf++) {
                ldx4(b1f[nf], boff + nf * 1280 + ko);
                ldx4(b2f[nf], boff + 5120 + nf * 1280 + ko);
            }
#pragma unroll
            for (int mf = 0; mf < 2; mf++)
#pragma unroll
                for (int j = 0; j < 4; j++) {
                    int nf = j >> 1, sub = (j & 1) * 2;
                    mma16816(acc[mf][j], a1f[mf], b1f[nf][sub], b1f[nf][sub + 1]);
                    mma16816(acc[mf][j], a1f[mf], b2f[nf][sub], b2f[nf][sub + 1]);
                    mma16816(acc[mf][j], a2f[mf], b1f[nf][sub], b1f[nf][sub + 1]);
                }
        }
        __syncthreads();
    }

    // ---- epilogue ----
    float* sMid = (float*)sm8;            // [128][16]
    float* sLb  = (float*)(sm8 + 8192);   // [16][64]
    for (int idx = tid; idx < 128 * RANK; idx += 256) {
        int row = idx >> 4, r = idx & 15;
        sMid[idx] = mid[(size_t)(m0 + row) * RANK + r];
    }
    for (int idx = tid; idx < RANK * 64; idx += 256) {
        int r = idx >> 6, c = idx & 63;
        sLb[idx] = lb[(size_t)r * N + n0 + c];
    }
    __syncthreads();

    float qs = is_qkv ? *qsp : 1.0f, qz = is_qkv ? *qzp : 0.0f;
    float qscale = 0.125f * qs;   // folds K's dequant scale + 1/sqrt(64) into Q
    int group = lane >> 2, tig = lane & 3;
#pragma unroll
    for (int mf = 0; mf < 2; mf++) {
#pragma unroll
        for (int half = 0; half < 2; half++) {
            int rloc = warp_m * 32 + mf * 16 + group + half * 8;
#pragma unroll
            for (int j = 0; j < 4; j++) {
                int cloc = warp_n * 32 + j * 8 + tig * 2;
                float d0 = acc[mf][j][half * 2];
                float d1 = acc[mf][j][half * 2 + 1];
                float lv0 = 0.0f, lv1 = 0.0f;
#pragma unroll
                for (int r = 0; r < RANK; r++) {
                    float mv = sMid[rloc * RANK + r];
                    lv0 += mv * sLb[r * 64 + cloc];
                    lv1 += mv * sLb[r * 64 + cloc + 1];
                }
                float bv0 = bias[n0 + cloc], bv1 = bias[n0 + cloc + 1];
                float v0 = d0 + bv0 + LSCALE * lv0;
                float v1 = d1 + bv1 + LSCALE * lv1;
                int m = m0 + rloc;
                int col = n0 + cloc;
                if (!is_qkv) {
                    *(float2*)&C[(size_t)m * N + col] = make_float2(v0, v1);
                } else {
                    int bq = m >> 11, t = m & 2047;
                    if (col < CDIM) {
                        int h = col >> 6, d = col & 63;
                        size_t off = (((size_t)(bq * NH + h)) * TT + t) * HD + d;
                        float s0 = v0 * qscale, s1 = v1 * qscale;
                        __nv_bfloat162 h1 = __floats2bfloat162_rn(s0, s1);
                        float2 hf = __bfloat1622float2(h1);
                        __nv_bfloat162 h2 = __floats2bfloat162_rn(s0 - hf.x, s1 - hf.y);
                        *(__nv_bfloat162*)(q1p + off) = h1;
                        *(__nv_bfloat162*)(q2p + off) = h2;
                    } else {
                        int cc = col - CDIM;
                        __nv_bfloat16* pl = (cc < CDIM) ? kqp : vqp;
                        if (cc >= CDIM) cc -= CDIM;
                        float r0 = fq_level(v0, qs, qz, m, col,     xf, wtf, bv0, lv0);
                        float r1 = fq_level(v1, qs, qz, m, col + 1, xf, wtf, bv1, lv1);
                        int h = cc >> 6, d = cc & 63;
                        size_t off = (((size_t)(bq * NH + h)) * TT + t) * HD + d;
                        // store exact integer levels (r - zp) in ONE bf16 plane
                        *(__nv_bfloat162*)(pl + off) =
                            __floats2bfloat162_rn(r0 - qz, r1 - qz);
                    }
                }
            }
        }
    }
}

// ---------------- HMMA flash attention (K/V exact integer planes) ----------------
// 128 threads (4 warps, 16 q-rows each), 64x64 tiles.
// S = (q1 + q2) @ Kint,  O = (p1 + p2) @ Vint, final scale by qs.
// smem: Q1@0, Q2@9216, stage st @18432+st*18432: K(9216), V(9216). Total 55296.
#define ATTN_SMEM 55296

__global__ __launch_bounds__(128) void attn_kernel(
    const __nv_bfloat16* __restrict__ q1p, const __nv_bfloat16* __restrict__ q2p,
    const __nv_bfloat16* __restrict__ kqp, const __nv_bfloat16* __restrict__ vqp,
    const float* __restrict__ qsp,
    __nv_bfloat16* __restrict__ a1p, __nv_bfloat16* __restrict__ a2p)
{
    extern __shared__ __align__(128) char smx[];
    uint32_t sb = smem_u32(smx);
    int tid = threadIdx.x, lane = tid & 31, w = tid >> 5;
    int bh = blockIdx.x;
    int qb = (int)gridDim.y - 1 - (int)blockIdx.y;
    size_t hbase = (size_t)bh * TT * HD;
    int group = lane >> 2, tig = lane & 3;
    float qs = __ldg(qsp);

    // Q load (rows qb*64..)
#pragma unroll
    for (int c = 0; c < 4; c++) {
        int ch = c * 128 + tid; int row = ch >> 3, cq = ch & 7;
        size_t g = hbase + (size_t)(qb * 64 + row) * HD + cq * 8;
        uint32_t so = row * 144 + cq * 16;
        cpa16(sb + so,        q1p + g);
        cpa16(sb + 9216 + so, q2p + g);
    }
#define LOADKV(buf, jb) do { \
    uint32_t s0_ = sb + 18432 + (buf) * 18432; \
    _Pragma("unroll") \
    for (int c = 0; c < 4; c++) { \
        int ch = c * 128 + tid; int row = ch >> 3, cq = ch & 7; \
        size_t g = hbase + (size_t)((jb) * 64 + row) * HD + cq * 8; \
        uint32_t so = row * 144 + cq * 16; \
        cpa16(s0_ + so,        kqp + g); \
        cpa16(s0_ + 9216 + so, vqp + g); \
    } \
} while (0)
    LOADKV(0, 0);
    asm volatile("cp.async.commit_group;" ::: "memory");

    uint32_t q1f[4][4], q2f[4][4];
    float mrow[2] = { -1e30f, -1e30f }, lrow[2] = { 0.0f, 0.0f };
    float oacc[8][4];
#pragma unroll
    for (int nb = 0; nb < 8; nb++)
#pragma unroll
        for (int e = 0; e < 4; e++) oacc[nb][e] = 0.0f;

    for (int j = 0; j <= qb; j++) {
        if (j < qb) {
            LOADKV((j + 1) & 1, j + 1);
            asm volatile("cp.async.commit_group;" ::: "memory");
            asm volatile("cp.async.wait_group 1;" ::: "memory");
        } else {
            asm volatile("cp.async.wait_group 0;" ::: "memory");
        }
        __syncthreads();

        if (j == 0) {   // hoist Q fragments once
            uint32_t qa = sb + (uint32_t)(w * 16 + (lane & 15)) * 144 + (uint32_t)(lane >> 4) * 16;
#pragma unroll
            for (int kk = 0; kk < 4; kk++) {
                ldx4(q1f[kk], qa + kk * 32);
                ldx4(q2f[kk], qa + 9216 + kk * 32);
            }
        }

        uint32_t stg = sb + 18432 + (uint32_t)(j & 1) * 18432;

        // S = (q1 + q2) K^T — K exact
        float sacc[8][4];
#pragma unroll
        for (int nb = 0; nb < 8; nb++)
#pragma unroll
            for (int e = 0; e < 4; e++) sacc[nb][e] = 0.0f;
#pragma unroll
        for (int kk = 0; kk < 4; kk++) {
#pragma unroll
            for (int nbp = 0; nbp < 4; nbp++) {
                uint32_t ka = stg + (uint32_t)(nbp * 16 + (lane & 7) + ((lane >> 4) & 1) * 8) * 144
                            + (uint32_t)((lane >> 3) & 1) * 16 + kk * 32;
                uint32_t kf[4];
                ldx4(kf, ka);
#pragma unroll
                for (int h = 0; h < 2; h++) {
                    int nb = nbp * 2 + h, sub = h * 2;
                    mma16816(sacc[nb], q1f[kk], kf[sub], kf[sub + 1]);
                    mma16816(sacc[nb], q2f[kk], kf[sub], kf[sub + 1]);
                }
            }
        }

        // causal mask on diagonal block
        if (j == qb) {
#pragma unroll
            for (int nb = 0; nb < 8; nb++)
#pragma unroll
                for (int e = 0; e < 2; e++) {
                    int rowl = w * 16 + group + e * 8;
                    int c0 = nb * 8 + tig * 2;
                    if (c0 > rowl)     sacc[nb][e * 2]     = -1e30f;
                    if (c0 + 1 > rowl) sacc[nb][e * 2 + 1] = -1e30f;
                }
        }

        // streaming softmax on fragments
        float mx[2] = { -1e30f, -1e30f };
#pragma unroll
        for (int nb = 0; nb < 8; nb++) {
            mx[0] = fmaxf(mx[0], fmaxf(sacc[nb][0], sacc[nb][1]));
            mx[1] = fmaxf(mx[1], fmaxf(sacc[nb][2], sacc[nb][3]));
        }
#pragma unroll
        for (int o = 1; o <= 2; o <<= 1) {
            mx[0] = fmaxf(mx[0], __shfl_xor_sync(0xffffffffu, mx[0], o));
            mx[1] = fmaxf(mx[1], __shfl_xor_sync(0xffffffffu, mx[1], o));
        }
        float al[2];
#pragma unroll
        for (int e = 0; e < 2; e++) {
            float mn = fmaxf(mrow[e], mx[e]);
            al[e] = __expf(mrow[e] - mn);
            mrow[e] = mn;
        }
        float rs[2] = { 0.0f, 0.0f };
#pragma unroll
        for (int nb = 0; nb < 8; nb++) {
#pragma unroll
            for (int e = 0; e < 2; e++) {
                float p0 = __expf(sacc[nb][e * 2]     - mrow[e]);
                float p1 = __expf(sacc[nb][e * 2 + 1] - mrow[e]);
                sacc[nb][e * 2] = p0; sacc[nb][e * 2 + 1] = p1;
                rs[e] += p0 + p1;
            }
        }
#pragma unroll
        for (int o = 1; o <= 2; o <<= 1) {
            rs[0] += __shfl_xor_sync(0xffffffffu, rs[0], o);
            rs[1] += __shfl_xor_sync(0xffffffffu, rs[1], o);
        }
#pragma unroll
        for (int e = 0; e < 2; e++) lrow[e] = lrow[e] * al[e] + rs[e];
#pragma unroll
        for (int nb = 0; nb < 8; nb++) {
            oacc[nb][0] *= al[0]; oacc[nb][1] *= al[0];
            oacc[nb][2] *= al[1]; oacc[nb][3] *= al[1];
        }

        // O += (p1 + p2) V — V exact
#pragma unroll
        for (int kk = 0; kk < 4; kk++) {
            int t0 = 2 * kk, t1 = 2 * kk + 1;
            uint32_t pa1[4], pa2[4];
            {
                __nv_bfloat162 h;
                float2 hf;
                h = __floats2bfloat162_rn(sacc[t0][0], sacc[t0][1]);
                hf = __bfloat1622float2(h); pa1[0] = *(uint32_t*)&h;
                h = __floats2bfloat162_rn(sacc[t0][0] - hf.x, sacc[t0][1] - hf.y);
                pa2[0] = *(uint32_t*)&h;
                h = __floats2bfloat162_rn(sacc[t0][2], sacc[t0][3]);
                hf = __bfloat1622float2(h); pa1[1] = *(uint32_t*)&h;
                h = __floats2bfloat162_rn(sacc[t0][2] - hf.x, sacc[t0][3] - hf.y);
                pa2[1] = *(uint32_t*)&h;
                h = __floats2bfloat162_rn(sacc[t1][0], sacc[t1][1]);
                hf = __bfloat1622float2(h); pa1[2] = *(uint32_t*)&h;
                h = __floats2bfloat162_rn(sacc[t1][0] - hf.x, sacc[t1][1] - hf.y);
                pa2[2] = *(uint32_t*)&h;
                h = __floats2bfloat162_rn(sacc[t1][2], sacc[t1][3]);
                hf = __bfloat1622float2(h); pa1[3] = *(uint32_t*)&h;
                h = __floats2bfloat162_rn(sacc[t1][2] - hf.x, sacc[t1][3] - hf.y);
                pa2[3] = *(uint32_t*)&h;
            }
#pragma unroll
            for (int nbp = 0; nbp < 4; nbp++) {
                uint32_t va = stg + 9216
                    + (uint32_t)(kk * 16 + (lane & 7) + ((lane >> 3) & 1) * 8) * 144
                    + nbp * 32 + (uint32_t)(lane >> 4) * 16;
                uint32_t vf[4];
                ldx4t(vf, va);
                mma16816(oacc[2 * nbp],     pa1, vf[0], vf[1]);
                mma16816(oacc[2 * nbp],     pa2, vf[0], vf[1]);
                mma16816(oacc[2 * nbp + 1], pa1, vf[2], vf[3]);
                mma16816(oacc[2 * nbp + 1], pa2, vf[2], vf[3]);
            }
        }
        __syncthreads();
    }

    // finalize: O = (acc / l) * qs -> bf16 split planes (token-major)
    int b = bh >> 4, h = bh & 15;
#pragma unroll
    for (int e = 0; e < 2; e++) {
        float inv = __fdiv_rn(1.0f, lrow[e]) * qs;
        int t = qb * 64 + w * 16 + group + e * 8;
        size_t mrow_off = ((size_t)(b * TT + t)) * CDIM + h * HD;
#pragma unroll
        for (int nb = 0; nb < 8; nb++) {
            float o0 = oacc[nb][e * 2] * inv;
            float o1 = oacc[nb][e * 2 + 1] * inv;
            int d = nb * 8 + tig * 2;
            __nv_bfloat162 h1 = __floats2bfloat162_rn(o0, o1);
            float2 hf = __bfloat1622float2(h1);
            __nv_bfloat162 h2 = __floats2bfloat162_rn(o0 - hf.x, o1 - hf.y);
            *(__nv_bfloat162*)(a1p + mrow_off + d) = h1;
            *(__nv_bfloat162*)(a2p + mrow_off + d) = h2;
        }
    }
}

// ---------------- launch ----------------
extern "C" void kernel_launch(void* const* d_in, const int* in_sizes, int n_in,
                              void* d_out, int out_size)
{
    const float* x       = (const float*)d_in[0];
    const float* w_attn  = (const float*)d_in[1];
    const float* b_attn  = (const float*)d_in[2];
    const float* la_attn = (const float*)d_in[3];
    const float* lb_attn = (const float*)d_in[4];
    const float* w_proj  = (const float*)d_in[5];
    const float* b_proj  = (const float*)d_in[6];
    const float* la_proj = (const float*)d_in[7];
    const float* lb_proj = (const float*)d_in[8];
    const float* ksc     = (const float*)d_in[9];
    const float* kzp     = (const float*)d_in[10];
    float* out = (float*)d_out;

    void* p;
    cudaGetSymbolAddress(&p, g_x1);   __nv_bfloat16* x1 = (__nv_bfloat16*)p;
    cudaGetSymbolAddress(&p, g_x2);   __nv_bfloat16* x2 = (__nv_bfloat16*)p;
    cudaGetSymbolAddress(&p, g_a1);   __nv_bfloat16* a1 = (__nv_bfloat16*)p;
    cudaGetSymbolAddress(&p, g_a2);   __nv_bfloat16* a2 = (__nv_bfloat16*)p;
    cudaGetSymbolAddress(&p, g_wt1a); __nv_bfloat16* wt1a = (__nv_bfloat16*)p;
    cudaGetSymbolAddress(&p, g_wt2a); __nv_bfloat16* wt2a = (__nv_bfloat16*)p;
    cudaGetSymbolAddress(&p, g_wt1p); __nv_bfloat16* wt1p = (__nv_bfloat16*)p;
    cudaGetSymbolAddress(&p, g_wt2p); __nv_bfloat16* wt2p = (__nv_bfloat16*)p;
    cudaGetSymbolAddress(&p, g_wtf);  float* wtf = (float*)p;
    cudaGetSymbolAddress(&p, g_q1);   __nv_bfloat16* q1 = (__nv_bfloat16*)p;
    cudaGetSymbolAddress(&p, g_q2);   __nv_bfloat16* q2 = (__nv_bfloat16*)p;
    cudaGetSymbolAddress(&p, g_kq);   __nv_bfloat16* kq = (__nv_bfloat16*)p;
    cudaGetSymbolAddress(&p, g_vq);   __nv_bfloat16* vq = (__nv_bfloat16*)p;
    cudaGetSymbolAddress(&p, g_mid);  float* mid  = (float*)p;
    cudaGetSymbolAddress(&p, g_mid2); float* mid2 = (float*)p;

    cudaFuncSetAttribute(gemm_mma_kernel,
                         cudaFuncAttributeMaxDynamicSharedMemorySize, GEMM_SMEM);
    cudaFuncSetAttribute(attn_kernel,
                         cudaFuncAttributeMaxDynamicSharedMemorySize, ATTN_SMEM);
    cudaFuncSetAttribute(lora_mid_kernel,
                         cudaFuncAttributeMaxDynamicSharedMemorySize, LORA_SMEM);
    cudaFuncSetAttribute(lora_mid2_kernel,
                         cudaFuncAttributeMaxDynamicSharedMemorySize, LORA_SMEM);

    // order chosen so a profiled launch #4 = QKV GEMM, #6 = attention
    split_kernel<<<(MTOT * CDIM / 4 + 255) / 256, 256>>>(x, x1, x2, MTOT * CDIM / 4);
    wsplit_kernel<<<dim3(N3C / 32, CDIM / 32), 256>>>(w_attn, wt1a, wt2a, wtf, N3C, CDIM);
    lora_mid_kernel<<<MTOT / 16, 256, LORA_SMEM>>>(x, la_attn, mid);
    gemm_mma_kernel<<<dim3(N3C / 64, MTOT / 128), 256, GEMM_SMEM>>>(
        x1, x2, wt1a, wt2a, b_attn, mid, lb_attn,
        (float*)0, N3C, 1, ksc, kzp, x, wtf, q1, q2, kq, vq);
    wsplit_kernel<<<dim3(CDIM / 32, CDIM / 32), 256>>>(w_proj, wt1p, wt2p, (float*)0, CDIM, CDIM);
    attn_kernel<<<dim3(BB * NH, TT / 64), 128, ATTN_SMEM>>>(
        q1, q2, kq, vq, ksc, a1, a2);
    lora_mid2_kernel<<<MTOT / 16, 256, LORA_SMEM>>>(a1, a2, la_proj, mid2);
    gemm_mma_kernel<<<dim3(CDIM / 64, MTOT / 128), 256, GEMM_SMEM>>>(
        a1, a2, wt1p, wt2p, b_proj, mid2, lb_proj,
        out, CDIM, 0, ksc, kzp, x, wtf,
        (__nv_bfloat16*)0, (__nv_bfloat16*)0, (__nv_bfloat16*)0, (__nv_bfloat16*)0);
}

// round 13
// speedup vs baseline: 6.1973x; 1.1790x over previous
#include <cuda_runtime.h>
#include <cuda_bf16.h>
#include <math.h>
#include <float.h>
#include <stdint.h>

#define BB    2
#define TT    2048
#define CDIM  1024
#define NH    16
#define HD    64
#define MTOT  (BB*TT)
#define N3C   (3*CDIM)
#define RANK  16
#define LSCALE 2.0f

// ---------------- portable MMA helpers ----------------
__device__ __forceinline__ uint32_t smem_u32(const void* p) {
    uint32_t a;
    asm("{ .reg .u64 t; cvta.to.shared.u64 t, %1; cvt.u32.u64 %0, t; }" : "=r"(a) : "l"(p));
    return a;
}
__device__ __forceinline__ void cpa16(uint32_t s, const void* g) {
    asm volatile("cp.async.cg.shared.global [%0], [%1], 16;" :: "r"(s), "l"(g));
}
__device__ __forceinline__ void ldx4(uint32_t* r, uint32_t a) {
    asm volatile("ldmatrix.sync.aligned.m8n8.x4.shared.b16 {%0,%1,%2,%3}, [%4];"
        : "=r"(r[0]), "=r"(r[1]), "=r"(r[2]), "=r"(r[3]) : "r"(a));
}
__device__ __forceinline__ void ldx4t(uint32_t* r, uint32_t a) {
    asm volatile("ldmatrix.sync.aligned.m8n8.x4.trans.shared.b16 {%0,%1,%2,%3}, [%4];"
        : "=r"(r[0]), "=r"(r[1]), "=r"(r[2]), "=r"(r[3]) : "r"(a));
}
__device__ __forceinline__ void mma16816(float* d, const uint32_t* a,
                                         uint32_t b0, uint32_t b1) {
    asm volatile("mma.sync.aligned.m16n8k16.row.col.f32.bf16.bf16.f32 "
        "{%0,%1,%2,%3}, {%4,%5,%6,%7}, {%8,%9}, {%0,%1,%2,%3};"
        : "+f"(d[0]), "+f"(d[1]), "+f"(d[2]), "+f"(d[3])
        : "r"(a[0]), "r"(a[1]), "r"(a[2]), "r"(a[3]), "r"(b0), "r"(b1));
}

// ---------------- scratch ----------------
__device__ __nv_bfloat16 g_x1[MTOT * CDIM];
__device__ __nv_bfloat16 g_x2[MTOT * CDIM];
__device__ __nv_bfloat16 g_a1[MTOT * CDIM];
__device__ __nv_bfloat16 g_a2[MTOT * CDIM];
__device__ __nv_bfloat16 g_wt1a[N3C * CDIM];
__device__ __nv_bfloat16 g_wt2a[N3C * CDIM];
__device__ __nv_bfloat16 g_wt1p[CDIM * CDIM];
__device__ __nv_bfloat16 g_wt2p[CDIM * CDIM];
__device__ float g_wtf[N3C * CDIM];            // fp32 W_attn^T for boundary recompute
__device__ __nv_bfloat16 g_q1[MTOT * CDIM];    // head-major planes [bh][t][64]
__device__ __nv_bfloat16 g_q2[MTOT * CDIM];
__device__ __nv_bfloat16 g_kq[MTOT * CDIM];    // K as exact integer levels (r - zp)
__device__ __nv_bfloat16 g_vq[MTOT * CDIM];    // V as exact integer levels (r - zp)
__device__ float g_mid [MTOT * RANK];
__device__ float g_mid2[MTOT * RANK];

// ---------------- split x -> bf16 hi/lo ----------------
__global__ __launch_bounds__(256) void split_kernel(
    const float* __restrict__ X, __nv_bfloat16* __restrict__ X1,
    __nv_bfloat16* __restrict__ X2, int total4)
{
    int i = blockIdx.x * 256 + threadIdx.x;
    if (i >= total4) return;
    float4 v = *(const float4*)(X + (size_t)i * 4);
    float a[4] = { v.x, v.y, v.z, v.w };
#pragma unroll
    for (int j = 0; j < 4; j++) {
        __nv_bfloat16 h1 = __float2bfloat16(a[j]);
        __nv_bfloat16 h2 = __float2bfloat16(a[j] - __bfloat162float(h1));
        X1[(size_t)i * 4 + j] = h1;
        X2[(size_t)i * 4 + j] = h2;
    }
}

// ---------------- W[K][N] -> Wt[N][K] bf16 hi/lo (+ optional fp32 copy) ----------------
__global__ __launch_bounds__(256) void wsplit_kernel(
    const float* __restrict__ W, __nv_bfloat16* __restrict__ Wt1,
    __nv_bfloat16* __restrict__ Wt2, float* __restrict__ Wtf, int N, int K)
{
    __shared__ float t[32][33];
    int tx = threadIdx.x & 31, ty = threadIdx.x >> 5;
    int n0 = blockIdx.x * 32, k0 = blockIdx.y * 32;
#pragma unroll
    for (int i = 0; i < 4; i++)
        t[ty + i * 8][tx] = W[(size_t)(k0 + ty + i * 8) * N + n0 + tx];
    __syncthreads();
#pragma unroll
    for (int i = 0; i < 4; i++) {
        int n = ty + i * 8;
        float v = t[tx][n];
        __nv_bfloat16 h1 = __float2bfloat16(v);
        __nv_bfloat16 h2 = __float2bfloat16(v - __bfloat162float(h1));
        Wt1[(size_t)(n0 + n) * K + k0 + tx] = h1;
        Wt2[(size_t)(n0 + n) * K + k0 + tx] = h2;
        if (Wtf) Wtf[(size_t)(n0 + n) * K + k0 + tx] = v;
    }
}

// ---------------- rank-16 LoRA mid: la fully staged (64KB) ----------------
#define LORA_SMEM (CDIM * RANK * 4)

__global__ __launch_bounds__(256) void lora_mid_kernel(
    const float* __restrict__ A, const float* __restrict__ la,
    float* __restrict__ out)
{
    extern __shared__ float las[];
    int tid = threadIdx.x;
    int r = tid & 15;
    int row = blockIdx.x * 16 + (tid >> 4);
    for (int idx = tid; idx < CDIM * RANK; idx += 256)
        las[idx] = la[idx];
    __syncthreads();
    const float* ap = A + (size_t)row * CDIM;
    float a0 = 0, a1 = 0, a2 = 0, a3 = 0;
#pragma unroll 8
    for (int k = 0; k < CDIM; k += 4) {
        float4 x4 = *(const float4*)(ap + k);
        a0 += x4.x * las[(k + 0) * RANK + r];
        a1 += x4.y * las[(k + 1) * RANK + r];
        a2 += x4.z * las[(k + 2) * RANK + r];
        a3 += x4.w * las[(k + 3) * RANK + r];
    }
    out[(size_t)row * RANK + r] = (a0 + a1) + (a2 + a3);
}

__global__ __launch_bounds__(256) void lora_mid2_kernel(
    const __nv_bfloat16* __restrict__ A1, const __nv_bfloat16* __restrict__ A2,
    const float* __restrict__ la, float* __restrict__ out)
{
    extern __shared__ float las[];
    int tid = threadIdx.x;
    int r = tid & 15;
    int row = blockIdx.x * 16 + (tid >> 4);
    for (int idx = tid; idx < CDIM * RANK; idx += 256)
        las[idx] = la[idx];
    __syncthreads();
    const __nv_bfloat16* a1r = A1 + (size_t)row * CDIM;
    const __nv_bfloat16* a2r = A2 + (size_t)row * CDIM;
    float a0 = 0, a1 = 0, a2 = 0, a3 = 0;
#pragma unroll 8
    for (int k = 0; k < CDIM; k += 4) {
        uint2 u1 = *(const uint2*)(a1r + k);
        uint2 u2 = *(const uint2*)(a2r + k);
        float2 p0 = __bfloat1622float2(*(const __nv_bfloat162*)&u1.x);
        float2 p1 = __bfloat1622float2(*(const __nv_bfloat162*)&u1.y);
        float2 q0 = __bfloat1622float2(*(const __nv_bfloat162*)&u2.x);
        float2 q1 = __bfloat1622float2(*(const __nv_bfloat162*)&u2.y);
        a0 += (p0.x + q0.x) * las[(k + 0) * RANK + r];
        a1 += (p0.y + q0.y) * las[(k + 1) * RANK + r];
        a2 += (p1.x + q1.x) * las[(k + 2) * RANK + r];
        a3 += (p1.y + q1.y) * las[(k + 3) * RANK + r];
    }
    out[(size_t)row * RANK + r] = (a0 + a1) + (a2 + a3);
}

// ---------------- fp32 recompute for quant-boundary elements ----------------
__device__ __noinline__ float exact_dot(const float* __restrict__ xr,
                                        const float* __restrict__ wc,
                                        float bv, float lv)
{
    float s0 = 0, s1 = 0, s2 = 0, s3 = 0, s4 = 0, s5 = 0, s6 = 0, s7 = 0;
#pragma unroll 4
    for (int k = 0; k < CDIM; k += 8) {
        float4 xa = __ldg((const float4*)(xr + k));
        float4 xb = __ldg((const float4*)(xr + k + 4));
        float4 wa = __ldg((const float4*)(wc + k));
        float4 wb = __ldg((const float4*)(wc + k + 4));
        s0 += xa.x * wa.x; s1 += xa.y * wa.y;
        s2 += xa.z * wa.z; s3 += xa.w * wa.w;
        s4 += xb.x * wb.x; s5 += xb.y * wb.y;
        s6 += xb.z * wb.z; s7 += xb.w * wb.w;
    }
    return ((s0 + s1) + (s2 + s3)) + ((s4 + s5) + (s6 + s7)) + bv + LSCALE * lv;
}
// returns clamped quant LEVEL r (plane stores r - qz, exact integer in bf16)
__device__ __forceinline__ float fq_level(float v, float qs, float qz, int m, int col,
        const float* xf, const float* wtf, float bv, float lv)
{
    float frac = __fdiv_rn(v, qs) + qz;
    float r = rintf(frac);
    if (0.5f - fabsf(frac - r) < 1e-3f) {
        v = exact_dot(xf + (size_t)m * CDIM, wtf + (size_t)col * CDIM, bv, lv);
        frac = __fdiv_rn(v, qs) + qz;
        r = rintf(frac);
    }
    return fminf(fmaxf(r, 0.0f), 255.0f);
}

// ---------------- bf16 split GEMM on mma.sync ----------------
// Block 128x64, 8 warps (4x2), warp tile 32x32, BK=32, K=1024.
// 3-stage cp.async pipeline (prefetch 2 ahead), 2 CTAs/SM guaranteed.
#define GSTG 30720
#define GEMM_SMEM (3 * GSTG)

__global__ __launch_bounds__(256, 2) void gemm_mma_kernel(
    const __nv_bfloat16* __restrict__ A1, const __nv_bfloat16* __restrict__ A2,
    const __nv_bfloat16* __restrict__ B1, const __nv_bfloat16* __restrict__ B2,
    const float* __restrict__ bias,
    const float* __restrict__ mid, const float* __restrict__ lb,
    float* __restrict__ C, int N, int is_qkv,
    const float* __restrict__ qsp, const float* __restrict__ qzp,
    const float* __restrict__ xf, const float* __restrict__ wtf,
    __nv_bfloat16* __restrict__ q1p, __nv_bfloat16* __restrict__ q2p,
    __nv_bfloat16* __restrict__ kqp, __nv_bfloat16* __restrict__ vqp)
{
    extern __shared__ __align__(128) char sm8[];
    int tid = threadIdx.x, wid = tid >> 5, lane = tid & 31;
    int warp_m = wid & 3, warp_n = wid >> 2;
    int m0 = blockIdx.y * 128, n0 = blockIdx.x * 64;
    uint32_t sb = smem_u32(sm8);

    float acc[2][4][4];
#pragma unroll
    for (int mf = 0; mf < 2; mf++)
#pragma unroll
        for (int j = 0; j < 4; j++)
#pragma unroll
            for (int e = 0; e < 4; e++) acc[mf][j][e] = 0.0f;

    int arow0 = (tid * 2) >> 2,      acq0 = (tid * 2) & 3;
    int arow1 = (tid * 2 + 1) >> 2,  acq1 = (tid * 2 + 1) & 3;
    int brow  = tid >> 2,            bcq  = tid & 3;
    const __nv_bfloat16* pA1 = A1 + (size_t)m0 * CDIM;
    const __nv_bfloat16* pA2 = A2 + (size_t)m0 * CDIM;
    const __nv_bfloat16* pB1 = B1 + (size_t)n0 * CDIM;
    const __nv_bfloat16* pB2 = B2 + (size_t)n0 * CDIM;

#define LOAD_STAGE(buf, kc) do { \
    uint32_t st_ = sb + (buf) * GSTG; \
    cpa16(st_ + arow0 * 80 + acq0 * 16,          pA1 + (size_t)arow0 * CDIM + (kc) + acq0 * 8); \
    cpa16(st_ + arow1 * 80 + acq1 * 16,          pA1 + (size_t)arow1 * CDIM + (kc) + acq1 * 8); \
    cpa16(st_ + 10240 + arow0 * 80 + acq0 * 16,  pA2 + (size_t)arow0 * CDIM + (kc) + acq0 * 8); \
    cpa16(st_ + 10240 + arow1 * 80 + acq1 * 16,  pA2 + (size_t)arow1 * CDIM + (kc) + acq1 * 8); \
    cpa16(st_ + 20480 + brow * 80 + bcq * 16,    pB1 + (size_t)brow * CDIM + (kc) + bcq * 8); \
    cpa16(st_ + 25600 + brow * 80 + bcq * 16,    pB2 + (size_t)brow * CDIM + (kc) + bcq * 8); \
    asm volatile("cp.async.commit_group;" ::: "memory"); \
} while (0)

    LOAD_STAGE(0, 0);
    LOAD_STAGE(1, 32);

    int buf = 0;
    for (int s = 0; s < 32; s++) {
        if (s + 2 < 32) {
            int nb = buf - 1; if (nb < 0) nb += 3;   // (s+2)%3
            LOAD_STAGE(nb, (s + 2) * 32);
            asm volatile("cp.async.wait_group 2;" ::: "memory");
        } else if (s + 1 < 32) {
            asm volatile("cp.async.wait_group 1;" ::: "memory");
        } else {
            asm volatile("cp.async.wait_group 0;" ::: "memory");
        }
        __syncthreads();

        uint32_t st = sb + (uint32_t)buf * GSTG;
        uint32_t aoff = st + (uint32_t)(warp_m * 32 + (lane & 15)) * 80 + (uint32_t)(lane >> 4) * 16;
        uint32_t boff = st + 20480 +
            (uint32_t)(warp_n * 32 + (lane & 7) + ((lane >> 4) & 1) * 8) * 80 +
            (uint32_t)((lane >> 3) & 1) * 16;
#pragma unroll
        for (int kk = 0; kk < 2; kk++) {
            uint32_t ko = kk * 32;
            uint32_t a1f[2][4], a2f[2][4], b1f[2][4], b2f[2][4];
#pragma unroll
            for (int mf = 0; mf < 2; mf++) {
                ldx4(a1f[mf], aoff + mf * 1280 + ko);
                ldx4(a2f[mf], aoff + 10240 + mf * 1280 + ko);
            }
#pragma unroll
            for (int nf = 0; nf < 2; nf++) {
                ldx4(b1f[nf], boff + nf * 1280 + ko);
                ldx4(b2f[nf], boff + 5120 + nf * 1280 + ko);
            }
#pragma unroll
            for (int mf = 0; mf < 2; mf++)
#pragma unroll
                for (int j = 0; j < 4; j++) {
                    int nf = j >> 1, sub = (j & 1) * 2;
                    mma16816(acc[mf][j], a1f[mf], b1f[nf][sub], b1f[nf][sub + 1]);
                    mma16816(acc[mf][j], a1f[mf], b2f[nf][sub], b2f[nf][sub + 1]);
                    mma16816(acc[mf][j], a2f[mf], b1f[nf][sub], b1f[nf][sub + 1]);
                }
        }
        __syncthreads();
        if (++buf == 3) buf = 0;
    }

    // ---- epilogue ----
    float* sMid = (float*)sm8;            // [128][16]
    float* sLb  = (float*)(sm8 + 8192);   // [16][64]
    for (int idx = tid; idx < 128 * RANK; idx += 256) {
        int row = idx >> 4, r = idx & 15;
        sMid[idx] = mid[(size_t)(m0 + row) * RANK + r];
    }
    for (int idx = tid; idx < RANK * 64; idx += 256) {
        int r = idx >> 6, c = idx & 63;
        sLb[idx] = lb[(size_t)r * N + n0 + c];
    }
    __syncthreads();

    float qs = is_qkv ? *qsp : 1.0f, qz = is_qkv ? *qzp : 0.0f;
    float qscale = 0.125f * qs;   // folds K's dequant scale + 1/sqrt(64) into Q
    int group = lane >> 2, tig = lane & 3;
#pragma unroll
    for (int mf = 0; mf < 2; mf++) {
#pragma unroll
        for (int half = 0; half < 2; half++) {
            int rloc = warp_m * 32 + mf * 16 + group + half * 8;
#pragma unroll
            for (int j = 0; j < 4; j++) {
                int cloc = warp_n * 32 + j * 8 + tig * 2;
                float d0 = acc[mf][j][half * 2];
                float d1 = acc[mf][j][half * 2 + 1];
                float lv0 = 0.0f, lv1 = 0.0f;
#pragma unroll
                for (int r = 0; r < RANK; r++) {
                    float mv = sMid[rloc * RANK + r];
                    lv0 += mv * sLb[r * 64 + cloc];
                    lv1 += mv * sLb[r * 64 + cloc + 1];
                }
                float bv0 = bias[n0 + cloc], bv1 = bias[n0 + cloc + 1];
                float v0 = d0 + bv0 + LSCALE * lv0;
                float v1 = d1 + bv1 + LSCALE * lv1;
                int m = m0 + rloc;
                int col = n0 + cloc;
                if (!is_qkv) {
                    *(float2*)&C[(size_t)m * N + col] = make_float2(v0, v1);
                } else {
                    int bq = m >> 11, t = m & 2047;
                    if (col < CDIM) {
                        int h = col >> 6, d = col & 63;
                        size_t off = (((size_t)(bq * NH + h)) * TT + t) * HD + d;
                        float s0 = v0 * qscale, s1 = v1 * qscale;
                        __nv_bfloat162 h1 = __floats2bfloat162_rn(s0, s1);
                        float2 hf = __bfloat1622float2(h1);
                        __nv_bfloat162 h2 = __floats2bfloat162_rn(s0 - hf.x, s1 - hf.y);
                        *(__nv_bfloat162*)(q1p + off) = h1;
                        *(__nv_bfloat162*)(q2p + off) = h2;
                    } else {
                        int cc = col - CDIM;
                        __nv_bfloat16* pl = (cc < CDIM) ? kqp : vqp;
                        if (cc >= CDIM) cc -= CDIM;
                        float r0 = fq_level(v0, qs, qz, m, col,     xf, wtf, bv0, lv0);
                        float r1 = fq_level(v1, qs, qz, m, col + 1, xf, wtf, bv1, lv1);
                        int h = cc >> 6, d = cc & 63;
                        size_t off = (((size_t)(bq * NH + h)) * TT + t) * HD + d;
                        // store exact integer levels (r - zp) in ONE bf16 plane
                        *(__nv_bfloat162*)(pl + off) =
                            __floats2bfloat162_rn(r0 - qz, r1 - qz);
                    }
                }
            }
        }
    }
}

// ---------------- HMMA flash attention (K/V exact integer planes) ----------------
// 128 threads (4 warps, 16 q-rows each), 64x64 tiles.
// S = (q1 + q2) @ Kint,  O = (p1 + p2) @ Vint, final scale by qs.
// smem: Q1@0, Q2@9216, stage st @18432+st*18432: K(9216), V(9216). Total 55296.
#define ATTN_SMEM 55296

__global__ __launch_bounds__(128) void attn_kernel(
    const __nv_bfloat16* __restrict__ q1p, const __nv_bfloat16* __restrict__ q2p,
    const __nv_bfloat16* __restrict__ kqp, const __nv_bfloat16* __restrict__ vqp,
    const float* __restrict__ qsp,
    __nv_bfloat16* __restrict__ a1p, __nv_bfloat16* __restrict__ a2p)
{
    extern __shared__ __align__(128) char smx[];
    uint32_t sb = smem_u32(smx);
    int tid = threadIdx.x, lane = tid & 31, w = tid >> 5;
    int bh = blockIdx.x;
    int qb = (int)gridDim.y - 1 - (int)blockIdx.y;
    size_t hbase = (size_t)bh * TT * HD;
    int group = lane >> 2, tig = lane & 3;
    float qs = __ldg(qsp);

    // Q load (rows qb*64..)
#pragma unroll
    for (int c = 0; c < 4; c++) {
        int ch = c * 128 + tid; int row = ch >> 3, cq = ch & 7;
        size_t g = hbase + (size_t)(qb * 64 + row) * HD + cq * 8;
        uint32_t so = row * 144 + cq * 16;
        cpa16(sb + so,        q1p + g);
        cpa16(sb + 9216 + so, q2p + g);
    }
#define LOADKV(buf, jb) do { \
    uint32_t s0_ = sb + 18432 + (buf) * 18432; \
    _Pragma("unroll") \
    for (int c = 0; c < 4; c++) { \
        int ch = c * 128 + tid; int row = ch >> 3, cq = ch & 7; \
        size_t g = hbase + (size_t)((jb) * 64 + row) * HD + cq * 8; \
        uint32_t so = row * 144 + cq * 16; \
        cpa16(s0_ + so,        kqp + g); \
        cpa16(s0_ + 9216 + so, vqp + g); \
    } \
} while (0)
    LOADKV(0, 0);
    asm volatile("cp.async.commit_group;" ::: "memory");

    uint32_t q1f[4][4], q2f[4][4];
    float mrow[2] = { -1e30f, -1e30f }, lrow[2] = { 0.0f, 0.0f };
    float oacc[8][4];
#pragma unroll
    for (int nb = 0; nb < 8; nb++)
#pragma unroll
        for (int e = 0; e < 4; e++) oacc[nb][e] = 0.0f;

    for (int j = 0; j <= qb; j++) {
        if (j < qb) {
            LOADKV((j + 1) & 1, j + 1);
            asm volatile("cp.async.commit_group;" ::: "memory");
            asm volatile("cp.async.wait_group 1;" ::: "memory");
        } else {
            asm volatile("cp.async.wait_group 0;" ::: "memory");
        }
        __syncthreads();

        if (j == 0) {   // hoist Q fragments once
            uint32_t qa = sb + (uint32_t)(w * 16 + (lane & 15)) * 144 + (uint32_t)(lane >> 4) * 16;
#pragma unroll
            for (int kk = 0; kk < 4; kk++) {
                ldx4(q1f[kk], qa + kk * 32);
                ldx4(q2f[kk], qa + 9216 + kk * 32);
            }
        }

        uint32_t stg = sb + 18432 + (uint32_t)(j & 1) * 18432;

        // S = (q1 + q2) K^T — K exact
        float sacc[8][4];
#pragma unroll
        for (int nb = 0; nb < 8; nb++)
#pragma unroll
            for (int e = 0; e < 4; e++) sacc[nb][e] = 0.0f;
#pragma unroll
        for (int kk = 0; kk < 4; kk++) {
#pragma unroll
            for (int nbp = 0; nbp < 4; nbp++) {
                uint32_t ka = stg + (uint32_t)(nbp * 16 + (lane & 7) + ((lane >> 4) & 1) * 8) * 144
                            + (uint32_t)((lane >> 3) & 1) * 16 + kk * 32;
                uint32_t kf[4];
                ldx4(kf, ka);
#pragma unroll
                for (int h = 0; h < 2; h++) {
                    int nb = nbp * 2 + h, sub = h * 2;
                    mma16816(sacc[nb], q1f[kk], kf[sub], kf[sub + 1]);
                    mma16816(sacc[nb], q2f[kk], kf[sub], kf[sub + 1]);
                }
            }
        }

        // causal mask on diagonal block
        if (j == qb) {
#pragma unroll
            for (int nb = 0; nb < 8; nb++)
#pragma unroll
                for (int e = 0; e < 2; e++) {
                    int rowl = w * 16 + group + e * 8;
                    int c0 = nb * 8 + tig * 2;
                    if (c0 > rowl)     sacc[nb][e * 2]     = -1e30f;
                    if (c0 + 1 > rowl) sacc[nb][e * 2 + 1] = -1e30f;
                }
        }

        // streaming softmax on fragments
        float mx[2] = { -1e30f, -1e30f };
#pragma unroll
        for (int nb = 0; nb < 8; nb++) {
            mx[0] = fmaxf(mx[0], fmaxf(sacc[nb][0], sacc[nb][1]));
            mx[1] = fmaxf(mx[1], fmaxf(sacc[nb][2], sacc[nb][3]));
        }
#pragma unroll
        for (int o = 1; o <= 2; o <<= 1) {
            mx[0] = fmaxf(mx[0], __shfl_xor_sync(0xffffffffu, mx[0], o));
            mx[1] = fmaxf(mx[1], __shfl_xor_sync(0xffffffffu, mx[1], o));
        }
        float al[2];
#pragma unroll
        for (int e = 0; e < 2; e++) {
            float mn = fmaxf(mrow[e], mx[e]);
            al[e] = __expf(mrow[e] - mn);
            mrow[e] = mn;
        }
        float rs[2] = { 0.0f, 0.0f };
#pragma unroll
        for (int nb = 0; nb < 8; nb++) {
#pragma unroll
            for (int e = 0; e < 2; e++) {
                float p0 = __expf(sacc[nb][e * 2]     - mrow[e]);
                float p1 = __expf(sacc[nb][e * 2 + 1] - mrow[e]);
                sacc[nb][e * 2] = p0; sacc[nb][e * 2 + 1] = p1;
                rs[e] += p0 + p1;
            }
        }
#pragma unroll
        for (int o = 1; o <= 2; o <<= 1) {
            rs[0] += __shfl_xor_sync(0xffffffffu, rs[0], o);
            rs[1] += __shfl_xor_sync(0xffffffffu, rs[1], o);
        }
#pragma unroll
        for (int e = 0; e < 2; e++) lrow[e] = lrow[e] * al[e] + rs[e];
#pragma unroll
        for (int nb = 0; nb < 8; nb++) {
            oacc[nb][0] *= al[0]; oacc[nb][1] *= al[0];
            oacc[nb][2] *= al[1]; oacc[nb][3] *= al[1];
        }

        // O += (p1 + p2) V — V exact
#pragma unroll
        for (int kk = 0; kk < 4; kk++) {
            int t0 = 2 * kk, t1 = 2 * kk + 1;
            uint32_t pa1[4], pa2[4];
            {
                __nv_bfloat162 h;
                float2 hf;
                h = __floats2bfloat162_rn(sacc[t0][0], sacc[t0][1]);
                hf = __bfloat1622float2(h); pa1[0] = *(uint32_t*)&h;
                h = __floats2bfloat162_rn(sacc[t0][0] - hf.x, sacc[t0][1] - hf.y);
                pa2[0] = *(uint32_t*)&h;
                h = __floats2bfloat162_rn(sacc[t0][2], sacc[t0][3]);
                hf = __bfloat1622float2(h); pa1[1] = *(uint32_t*)&h;
                h = __floats2bfloat162_rn(sacc[t0][2] - hf.x, sacc[t0][3] - hf.y);
                pa2[1] = *(uint32_t*)&h;
                h = __floats2bfloat162_rn(sacc[t1][0], sacc[t1][1]);
                hf = __bfloat1622float2(h); pa1[2] = *(uint32_t*)&h;
                h = __floats2bfloat162_rn(sacc[t1][0] - hf.x, sacc[t1][1] - hf.y);
                pa2[2] = *(uint32_t*)&h;
                h = __floats2bfloat162_rn(sacc[t1][2], sacc[t1][3]);
                hf = __bfloat1622float2(h); pa1[3] = *(uint32_t*)&h;
                h = __floats2bfloat162_rn(sacc[t1][2] - hf.x, sacc[t1][3] - hf.y);
                pa2[3] = *(uint32_t*)&h;
            }
#pragma unroll
            for (int nbp = 0; nbp < 4; nbp++) {
                uint32_t va = stg + 9216
                    + (uint32_t)(kk * 16 + (lane & 7) + ((lane >> 3) & 1) * 8) * 144
                    + nbp * 32 + (uint32_t)(lane >> 4) * 16;
                uint32_t vf[4];
                ldx4t(vf, va);
                mma16816(oacc[2 * nbp],     pa1, vf[0], vf[1]);
                mma16816(oacc[2 * nbp],     pa2, vf[0], vf[1]);
                mma16816(oacc[2 * nbp + 1], pa1, vf[2], vf[3]);
                mma16816(oacc[2 * nbp + 1], pa2, vf[2], vf[3]);
            }
        }
        __syncthreads();
    }

    // finalize: O = (acc / l) * qs -> bf16 split planes (token-major)
    int b = bh >> 4, h = bh & 15;
#pragma unroll
    for (int e = 0; e < 2; e++) {
        float inv = __fdiv_rn(1.0f, lrow[e]) * qs;
        int t = qb * 64 + w * 16 + group + e * 8;
        size_t mrow_off = ((size_t)(b * TT + t)) * CDIM + h * HD;
#pragma unroll
        for (int nb = 0; nb < 8; nb++) {
            float o0 = oacc[nb][e * 2] * inv;
            float o1 = oacc[nb][e * 2 + 1] * inv;
            int d = nb * 8 + tig * 2;
            __nv_bfloat162 h1 = __floats2bfloat162_rn(o0, o1);
            float2 hf = __bfloat1622float2(h1);
            __nv_bfloat162 h2 = __floats2bfloat162_rn(o0 - hf.x, o1 - hf.y);
            *(__nv_bfloat162*)(a1p + mrow_off + d) = h1;
            *(__nv_bfloat162*)(a2p + mrow_off + d) = h2;
        }
    }
}

// ---------------- launch ----------------
extern "C" void kernel_launch(void* const* d_in, const int* in_sizes, int n_in,
                              void* d_out, int out_size)
{
    const float* x       = (const float*)d_in[0];
    const float* w_attn  = (const float*)d_in[1];
    const float* b_attn  = (const float*)d_in[2];
    const float* la_attn = (const float*)d_in[3];
    const float* lb_attn = (const float*)d_in[4];
    const float* w_proj  = (const float*)d_in[5];
    const float* b_proj  = (const float*)d_in[6];
    const float* la_proj = (const float*)d_in[7];
    const float* lb_proj = (const float*)d_in[8];
    const float* ksc     = (const float*)d_in[9];
    const float* kzp     = (const float*)d_in[10];
    float* out = (float*)d_out;

    void* p;
    cudaGetSymbolAddress(&p, g_x1);   __nv_bfloat16* x1 = (__nv_bfloat16*)p;
    cudaGetSymbolAddress(&p, g_x2);   __nv_bfloat16* x2 = (__nv_bfloat16*)p;
    cudaGetSymbolAddress(&p, g_a1);   __nv_bfloat16* a1 = (__nv_bfloat16*)p;
    cudaGetSymbolAddress(&p, g_a2);   __nv_bfloat16* a2 = (__nv_bfloat16*)p;
    cudaGetSymbolAddress(&p, g_wt1a); __nv_bfloat16* wt1a = (__nv_bfloat16*)p;
    cudaGetSymbolAddress(&p, g_wt2a); __nv_bfloat16* wt2a = (__nv_bfloat16*)p;
    cudaGetSymbolAddress(&p, g_wt1p); __nv_bfloat16* wt1p = (__nv_bfloat16*)p;
    cudaGetSymbolAddress(&p, g_wt2p); __nv_bfloat16* wt2p = (__nv_bfloat16*)p;
    cudaGetSymbolAddress(&p, g_wtf);  float* wtf = (float*)p;
    cudaGetSymbolAddress(&p, g_q1);   __nv_bfloat16* q1 = (__nv_bfloat16*)p;
    cudaGetSymbolAddress(&p, g_q2);   __nv_bfloat16* q2 = (__nv_bfloat16*)p;
    cudaGetSymbolAddress(&p, g_kq);   __nv_bfloat16* kq = (__nv_bfloat16*)p;
    cudaGetSymbolAddress(&p, g_vq);   __nv_bfloat16* vq = (__nv_bfloat16*)p;
    cudaGetSymbolAddress(&p, g_mid);  float* mid  = (float*)p;
    cudaGetSymbolAddress(&p, g_mid2); float* mid2 = (float*)p;

    cudaFuncSetAttribute(gemm_mma_kernel,
                         cudaFuncAttributeMaxDynamicSharedMemorySize, GEMM_SMEM);
    cudaFuncSetAttribute(attn_kernel,
                         cudaFuncAttributeMaxDynamicSharedMemorySize, ATTN_SMEM);
    cudaFuncSetAttribute(lora_mid_kernel,
                         cudaFuncAttributeMaxDynamicSharedMemorySize, LORA_SMEM);
    cudaFuncSetAttribute(lora_mid2_kernel,
                         cudaFuncAttributeMaxDynamicSharedMemorySize, LORA_SMEM);

    split_kernel<<<(MTOT * CDIM / 4 + 255) / 256, 256>>>(x, x1, x2, MTOT * CDIM / 4);
    wsplit_kernel<<<dim3(N3C / 32, CDIM / 32), 256>>>(w_attn, wt1a, wt2a, wtf, N3C, CDIM);
    lora_mid_kernel<<<MTOT / 16, 256, LORA_SMEM>>>(x, la_attn, mid);
    gemm_mma_kernel<<<dim3(N3C / 64, MTOT / 128), 256, GEMM_SMEM>>>(
        x1, x2, wt1a, wt2a, b_attn, mid, lb_attn,
        (float*)0, N3C, 1, ksc, kzp, x, wtf, q1, q2, kq, vq);
    wsplit_kernel<<<dim3(CDIM / 32, CDIM / 32), 256>>>(w_proj, wt1p, wt2p, (float*)0, CDIM, CDIM);
    attn_kernel<<<dim3(BB * NH, TT / 64), 128, ATTN_SMEM>>>(
        q1, q2, kq, vq, ksc, a1, a2);
    lora_mid2_kernel<<<MTOT / 16, 256, LORA_SMEM>>>(a1, a2, la_proj, mid2);
    gemm_mma_kernel<<<dim3(CDIM / 64, MTOT / 128), 256, GEMM_SMEM>>>(
        a1, a2, wt1p, wt2p, b_proj, mid2, lb_proj,
        out, CDIM, 0, ksc, kzp, x, wtf,
        (__nv_bfloat16*)0, (__nv_bfloat16*)0, (__nv_bfloat16*)0, (__nv_bfloat16*)0);
}